// round 8
// baseline (speedup 1.0000x reference)
#include <cuda_runtime.h>
#include <cuda_bf16.h>
#include <cuda_fp16.h>
#include <cstdint>

#define NP 100000
#define NA 50000
#define EPP 1600000
#define EAP 800000
#define EPA 800000

// ---------------- scratch ----------------------------------------------------
__device__ __align__(16) __half g_hs[NP * 128];    // transformed src feats (fp16)
__device__ __align__(16) float g_es[NP * 4];
__device__ __align__(16) float g_ed[3 * NP * 4];
__device__ __align__(16) float g_accp[NP * 128];
__device__ __align__(16) float g_acca[NA * 128];
__device__ __align__(16) float g_vd1[3 * 128 * 4];
__device__ __align__(16) float g_vd2[3 * 128 * 4];
// CSR scratch
__device__ int g_off_pp[NP + 1];
__device__ int g_off_ap[NP + 1];
__device__ int g_off_pa[NA + 1];
__device__ int g_srt[EPP + EAP + EPA];
__device__ int g_writer[NP];

// ---------------- helpers ----------------------------------------------------
__device__ __forceinline__ float lrelu(float x) { return x > 0.f ? x : 0.2f * x; }

__device__ __forceinline__ unsigned long long pack2(float lo, float hi) {
    unsigned long long r;
    asm("mov.b64 %0, {%1, %2};" : "=l"(r) : "f"(lo), "f"(hi));
    return r;
}
__device__ __forceinline__ void fma2(unsigned long long& d,
                                     unsigned long long a, unsigned long long b) {
    asm("fma.rn.f32x2 %0, %1, %2, %0;" : "+l"(d) : "l"(a), "l"(b));
}
__device__ __forceinline__ float2 unpack2(unsigned long long v) {
    float lo, hi;
    asm("mov.b64 {%0, %1}, %2;" : "=f"(lo), "=f"(hi) : "l"(v));
    return make_float2(lo, hi);
}

// ---------------- CSR build kernels -------------------------------------------
__global__ void zero_int(int* __restrict__ p, int n) {
    int i = blockIdx.x * blockDim.x + threadIdx.x;
    if (i < n) p[i] = 0;
}
__global__ void count_kernel(const int* __restrict__ dst, int* __restrict__ off, int E) {
    int e = blockIdx.x * blockDim.x + threadIdx.x;
    if (e < E) atomicAdd(&off[dst[e] + 1], 1);
}
// in-place inclusive scan of off[0..n-1] (single block, 1024 thr, 4/thread);
// writer[i] = scanned off[i] for i < nw
__global__ void __launch_bounds__(1024)
scan_writer(int* __restrict__ off, int* __restrict__ writer, int n, int nw) {
    __shared__ int ssum[1024];
    int tid = threadIdx.x;
    int running = 0;
    for (int base = 0; base < n; base += 4096) {
        int idx = base + tid * 4;
        int v0 = idx + 0 < n ? off[idx + 0] : 0;
        int v1 = idx + 1 < n ? off[idx + 1] : 0;
        int v2 = idx + 2 < n ? off[idx + 2] : 0;
        int v3 = idx + 3 < n ? off[idx + 3] : 0;
        int p0 = v0, p1 = p0 + v1, p2 = p1 + v2, p3 = p2 + v3;
        ssum[tid] = p3;
        __syncthreads();
        for (int o = 1; o < 1024; o <<= 1) {
            int val = 0;
            if (tid >= o) val = ssum[tid - o];
            __syncthreads();
            if (tid >= o) ssum[tid] += val;
            __syncthreads();
        }
        int excl = running + (tid ? ssum[tid - 1] : 0);
        int total = ssum[1023];
        __syncthreads();
        int s0 = excl + p0, s1 = excl + p1, s2 = excl + p2, s3 = excl + p3;
        if (idx + 0 < n) { off[idx + 0] = s0; if (idx + 0 < nw) writer[idx + 0] = s0; }
        if (idx + 1 < n) { off[idx + 1] = s1; if (idx + 1 < nw) writer[idx + 1] = s1; }
        if (idx + 2 < n) { off[idx + 2] = s2; if (idx + 2 < nw) writer[idx + 2] = s2; }
        if (idx + 3 < n) { off[idx + 3] = s3; if (idx + 3 < nw) writer[idx + 3] = s3; }
        running += total;
    }
}
__global__ void scatter_kernel(const int* __restrict__ src, const int* __restrict__ dst,
                               int* __restrict__ writer, int* __restrict__ srt, int E) {
    int e = blockIdx.x * blockDim.x + threadIdx.x;
    if (e >= E) return;
    int pos = atomicAdd(&writer[dst[e]], 1);
    srt[pos] = src[e];
}

// ---------------- SGEMM (f32x2) + fused es epilogue, fp16 C output ------------
#define BM 128
#define BN 64
#define BK 16
template <int CC>
__global__ void __launch_bounds__(256)
sgemm_es(const float* __restrict__ A, const float* __restrict__ B,
         __half* __restrict__ C, float* __restrict__ es,
         const float* __restrict__ a_s, int M, int N) {
    const int K = 128;
    __shared__ float As[2][BK][BM + 4];
    __shared__ float Bs[2][BK][BN];
    int tid = threadIdx.x;
    int m0 = blockIdx.y * BM, n0 = blockIdx.x * BN;

    int aRow = tid >> 1;
    int aC4 = (tid & 1) * 2;
    int bK = tid >> 4;
    int bC4 = tid & 15;
    int ty = tid >> 4;
    int tx = tid & 15;

    unsigned long long acc2[4][4];
#pragma unroll
    for (int ip = 0; ip < 4; ip++)
#pragma unroll
        for (int j = 0; j < 4; j++) acc2[ip][j] = 0ull;

    float4 ra0, ra1, rb;
    auto loadg = [&](int k0) {
        int m = m0 + aRow;
        if (m < M) {
            ra0 = *(const float4*)(A + (size_t)m * K + k0 + aC4 * 4);
            ra1 = *(const float4*)(A + (size_t)m * K + k0 + aC4 * 4 + 4);
        } else {
            ra0 = make_float4(0.f, 0.f, 0.f, 0.f);
            ra1 = ra0;
        }
        rb = *(const float4*)(B + (size_t)(k0 + bK) * N + n0 + bC4 * 4);
    };
    auto stores = [&](int buf) {
        As[buf][aC4 * 4 + 0][aRow] = ra0.x;
        As[buf][aC4 * 4 + 1][aRow] = ra0.y;
        As[buf][aC4 * 4 + 2][aRow] = ra0.z;
        As[buf][aC4 * 4 + 3][aRow] = ra0.w;
        As[buf][aC4 * 4 + 4][aRow] = ra1.x;
        As[buf][aC4 * 4 + 5][aRow] = ra1.y;
        As[buf][aC4 * 4 + 6][aRow] = ra1.z;
        As[buf][aC4 * 4 + 7][aRow] = ra1.w;
        *(float4*)&Bs[buf][bK][bC4 * 4] = rb;
    };

    loadg(0);
    stores(0);
    __syncthreads();

    const int NCH = K / BK;
#pragma unroll
    for (int c = 0; c < NCH; c++) {
        if (c + 1 < NCH) loadg((c + 1) * BK);
        int buf = c & 1;
#pragma unroll
        for (int k = 0; k < BK; k++) {
            float4 a0 = *(const float4*)&As[buf][k][ty * 8];
            float4 a1 = *(const float4*)&As[buf][k][ty * 8 + 4];
            float4 b = *(const float4*)&Bs[buf][k][tx * 4];
            unsigned long long ap[4] = {pack2(a0.x, a0.y), pack2(a0.z, a0.w),
                                        pack2(a1.x, a1.y), pack2(a1.z, a1.w)};
            unsigned long long bb[4] = {pack2(b.x, b.x), pack2(b.y, b.y),
                                        pack2(b.z, b.z), pack2(b.w, b.w)};
#pragma unroll
            for (int ip = 0; ip < 4; ip++)
#pragma unroll
                for (int j = 0; j < 4; j++) fma2(acc2[ip][j], ap[ip], bb[j]);
        }
        if (c + 1 < NCH) stores((c + 1) & 1);
        __syncthreads();
    }

    float accf[8][4];
#pragma unroll
    for (int ip = 0; ip < 4; ip++)
#pragma unroll
        for (int j = 0; j < 4; j++) {
            float2 v = unpack2(acc2[ip][j]);
            accf[2 * ip + 0][j] = v.x;
            accf[2 * ip + 1][j] = v.y;
        }

    {
        constexpr int RW = CC / 4;
        float4 a4 = *(const float4*)(a_s + n0 + tx * 4);
        int h = (n0 + tx * 4) / CC;
#pragma unroll
        for (int i = 0; i < 8; i++) {
            float pv = accf[i][0] * a4.x + accf[i][1] * a4.y +
                       accf[i][2] * a4.z + accf[i][3] * a4.w;
#pragma unroll
            for (int off = RW / 2; off > 0; off >>= 1)
                pv += __shfl_down_sync(0xffffffffu, pv, off, RW);
            int m = m0 + ty * 8 + i;
            if (m < M && (tx & (RW - 1)) == 0) es[m * 4 + h] = pv;
        }
    }

#pragma unroll
    for (int i = 0; i < 8; i++) {
        int m = m0 + ty * 8 + i;
        if (m < M) {
            union { __half2 h[2]; uint2 u; } cv;
            cv.h[0] = __floats2half2_rn(accf[i][0], accf[i][1]);
            cv.h[1] = __floats2half2_rn(accf[i][2], accf[i][3]);
            *(uint2*)(C + (size_t)m * N + n0 + tx * 4) = cv.u;
        }
    }
}

// ---------------- vd folding ---------------------------------------------------
__global__ void compute_vd(const float* __restrict__ Wd1, const float* __restrict__ ad1,
                           const float* __restrict__ Wd2, const float* __restrict__ ad2,
                           float* __restrict__ vd1, float* __restrict__ vd2) {
    int i = blockIdx.x * blockDim.x + threadIdx.x;
    if (i >= 2 * 3 * 128 * 4) return;
    int layer = i >= 3 * 128 * 4;
    int ii = i - layer * 3 * 128 * 4;
    int h = ii & 3;
    int f = (ii >> 2) & 127;
    int r = ii >> 9;
    int D = layer ? 64 : 128;
    int C = D / 4;
    const float* W = (layer ? Wd2 : Wd1) + (size_t)r * 128 * D + (size_t)f * D + h * C;
    const float* a = (layer ? ad2 : ad1) + r * 4 * C + h * C;
    float s = 0.f;
    for (int c = 0; c < C; c++) s += W[c] * a[c];
    (layer ? vd2 : vd1)[r * 512 + f * 4 + h] = s;
}

// -------- ed, thread-per-node, TWO relations, smem vd, f32x2 -------------------
__global__ void __launch_bounds__(256)
ed_nodes2(const float* __restrict__ x,
          const float* __restrict__ vdA, const float* __restrict__ vdB,
          float* __restrict__ edA, float* __restrict__ edB, int N) {
    __shared__ __align__(16) float sv[1024];
    int t = threadIdx.x;
    ((float4*)sv)[t] = (t < 128) ? ((const float4*)vdA)[t]
                                 : ((const float4*)vdB)[t - 128];
    __syncthreads();
    int n = blockIdx.x * blockDim.x + t;
    if (n >= N) return;
    unsigned long long accA[2] = {0ull, 0ull}, accB[2] = {0ull, 0ull};
    const float4* xr = (const float4*)(x + (size_t)n * 128);
#pragma unroll 8
    for (int r = 0; r < 32; r++) {
        float4 xv = xr[r];
#pragma unroll
        for (int j = 0; j < 4; j++) {
            float xs = j == 0 ? xv.x : j == 1 ? xv.y : j == 2 ? xv.z : xv.w;
            unsigned long long xp = pack2(xs, xs);
            ulonglong2 va = *(const ulonglong2*)&sv[(4 * r + j) * 4];
            fma2(accA[0], xp, va.x);
            fma2(accA[1], xp, va.y);
            ulonglong2 vb = *(const ulonglong2*)&sv[512 + (4 * r + j) * 4];
            fma2(accB[0], xp, vb.x);
            fma2(accB[1], xp, vb.y);
        }
    }
    float2 a0 = unpack2(accA[0]), a1 = unpack2(accA[1]);
    float2 b0 = unpack2(accB[0]), b1 = unpack2(accB[1]);
    ((float4*)edA)[n] = make_float4(a0.x, a0.y, a1.x, a1.y);
    ((float4*)edB)[n] = make_float4(b0.x, b0.y, b1.x, b1.y);
}

__global__ void __launch_bounds__(256)
ed_nodes1(const float* __restrict__ x, const float* __restrict__ vd,
          float* __restrict__ ed, int N) {
    __shared__ __align__(16) float sv[512];
    int t = threadIdx.x;
    if (t < 128) ((float4*)sv)[t] = ((const float4*)vd)[t];
    __syncthreads();
    int n = blockIdx.x * blockDim.x + t;
    if (n >= N) return;
    unsigned long long acc[2] = {0ull, 0ull};
    const float4* xr = (const float4*)(x + (size_t)n * 128);
#pragma unroll 8
    for (int r = 0; r < 32; r++) {
        float4 xv = xr[r];
#pragma unroll
        for (int j = 0; j < 4; j++) {
            float xs = j == 0 ? xv.x : j == 1 ? xv.y : j == 2 ? xv.z : xv.w;
            unsigned long long xp = pack2(xs, xs);
            ulonglong2 va = *(const ulonglong2*)&sv[(4 * r + j) * 4];
            fma2(acc[0], xp, va.x);
            fma2(acc[1], xp, va.y);
        }
    }
    float2 a0 = unpack2(acc[0]), a1 = unpack2(acc[1]);
    ((float4*)ed)[n] = make_float4(a0.x, a0.y, a1.x, a1.y);
}

// -------- GATHER conv: warp per dst node; fused softmax+agg+norm+bias/relu -----
template <int D>
__global__ void __launch_bounds__(256)
gat_gather(const int* __restrict__ off, const int* __restrict__ srt,
           const float* __restrict__ es, const float* __restrict__ ed,
           const __half* __restrict__ hs, float* __restrict__ acc,
           int Nd, int add, const float* __restrict__ bias0,
           const float* __restrict__ bias1, int relu) {
    constexpr int CPL = D / 32;            // channels per lane: 4 or 2
    int warp = (blockIdx.x * blockDim.x + threadIdx.x) >> 5;
    int lane = threadIdx.x & 31;
    if (warp >= Nd) return;
    int d = warp;
    int start = off[d], end = off[d + 1];
    float4 edv = ((const float4*)ed)[d];
    int h = lane >> 3;                     // head for this lane's channels
    float a0 = 0.f, a1 = 0.f, a2 = 0.f, a3 = 0.f;
    float4 den = make_float4(0.f, 0.f, 0.f, 0.f);

    for (int base = start; base < end; base += 32) {
        int i = base + lane;
        int s = 0;
        float4 ee = make_float4(0.f, 0.f, 0.f, 0.f);
        if (i < end) {
            s = srt[i];
            float4 esv = ((const float4*)es)[s];
            ee.x = __expf(lrelu(esv.x + edv.x));
            ee.y = __expf(lrelu(esv.y + edv.y));
            ee.z = __expf(lrelu(esv.z + edv.z));
            ee.w = __expf(lrelu(esv.w + edv.w));
        }
        den.x += ee.x; den.y += ee.y; den.z += ee.z; den.w += ee.w;
        int cnt = min(32, end - base);
        for (int j = 0; j < cnt; j++) {
            int sj = __shfl_sync(0xffffffffu, s, j);
            float e0 = __shfl_sync(0xffffffffu, ee.x, j);
            float e1 = __shfl_sync(0xffffffffu, ee.y, j);
            float e2 = __shfl_sync(0xffffffffu, ee.z, j);
            float e3 = __shfl_sync(0xffffffffu, ee.w, j);
            float aj = h == 0 ? e0 : h == 1 ? e1 : h == 2 ? e2 : e3;
            if (D == 128) {
                union { uint2 u; __half2 h2[2]; } cv;
                cv.u = *(const uint2*)(hs + (size_t)sj * D + lane * 4);
                float2 v01 = __half22float2(cv.h2[0]);
                float2 v23 = __half22float2(cv.h2[1]);
                a0 += aj * v01.x; a1 += aj * v01.y;
                a2 += aj * v23.x; a3 += aj * v23.y;
            } else {
                union { unsigned u; __half2 h2; } cv;
                cv.u = *(const unsigned*)(hs + (size_t)sj * D + lane * 2);
                float2 v = __half22float2(cv.h2);
                a0 += aj * v.x; a1 += aj * v.y;
            }
        }
    }
    // warp-reduce den (all lanes get totals)
#pragma unroll
    for (int o = 16; o; o >>= 1) {
        den.x += __shfl_xor_sync(0xffffffffu, den.x, o);
        den.y += __shfl_xor_sync(0xffffffffu, den.y, o);
        den.z += __shfl_xor_sync(0xffffffffu, den.z, o);
        den.w += __shfl_xor_sync(0xffffffffu, den.w, o);
    }
    float dh = h == 0 ? den.x : h == 1 ? den.y : h == 2 ? den.z : den.w;
    float inv = 1.f / (dh + 1e-16f);
    int cb = lane * CPL;
    float* dp = acc + (size_t)d * D + cb;
    if (D == 128) {
        float4 o = make_float4(a0 * inv, a1 * inv, a2 * inv, a3 * inv);
        if (add) {
            float4 pa = *(const float4*)dp;
            o.x += pa.x; o.y += pa.y; o.z += pa.z; o.w += pa.w;
        }
        if (bias0) {
            float4 b = *(const float4*)(bias0 + cb);
            o.x += b.x; o.y += b.y; o.z += b.z; o.w += b.w;
        }
        if (bias1) {
            float4 b = *(const float4*)(bias1 + cb);
            o.x += b.x; o.y += b.y; o.z += b.z; o.w += b.w;
        }
        if (relu) {
            o.x = fmaxf(o.x, 0.f); o.y = fmaxf(o.y, 0.f);
            o.z = fmaxf(o.z, 0.f); o.w = fmaxf(o.w, 0.f);
        }
        *(float4*)dp = o;
    } else {
        float2 o = make_float2(a0 * inv, a1 * inv);
        if (add) {
            float2 pa = *(const float2*)dp;
            o.x += pa.x; o.y += pa.y;
        }
        if (bias0) {
            float2 b = *(const float2*)(bias0 + cb);
            o.x += b.x; o.y += b.y;
        }
        if (bias1) {
            float2 b = *(const float2*)(bias1 + cb);
            o.x += b.x; o.y += b.y;
        }
        if (relu) {
            o.x = fmaxf(o.x, 0.f); o.y = fmaxf(o.y, 0.f);
        }
        *(float2*)dp = o;
    }
}

// =============================================================================
extern "C" void kernel_launch(void* const* d_in, const int* in_sizes, int n_in,
                              void* d_out, int out_size) {
    const float* x_p = (const float*)d_in[0];
    const float* x_a = (const float*)d_in[1];
    const int* src_pp = (const int*)d_in[2];
    const int* dst_pp = (const int*)d_in[3];
    const int* src_ap = (const int*)d_in[4];
    const int* dst_ap = (const int*)d_in[5];
    const int* src_pa = (const int*)d_in[6];
    const int* dst_pa = (const int*)d_in[7];
    const float* Wsrc1 = (const float*)d_in[8];
    const float* Wdst1 = (const float*)d_in[9];
    const float* asrc1 = (const float*)d_in[10];
    const float* adst1 = (const float*)d_in[11];
    const float* b1 = (const float*)d_in[12];
    const float* Wsrc2 = (const float*)d_in[13];
    const float* Wdst2 = (const float*)d_in[14];
    const float* asrc2 = (const float*)d_in[15];
    const float* adst2 = (const float*)d_in[16];
    const float* b2 = (const float*)d_in[17];
    float* out = (float*)d_out;

    void* p;
    cudaGetSymbolAddress(&p, g_hs);     __half* hs  = (__half*)p;
    cudaGetSymbolAddress(&p, g_es);     float* es   = (float*)p;
    cudaGetSymbolAddress(&p, g_ed);     float* ed   = (float*)p;
    cudaGetSymbolAddress(&p, g_accp);   float* accp = (float*)p;
    cudaGetSymbolAddress(&p, g_acca);   float* acca = (float*)p;
    cudaGetSymbolAddress(&p, g_vd1);    float* vd1  = (float*)p;
    cudaGetSymbolAddress(&p, g_vd2);    float* vd2  = (float*)p;
    cudaGetSymbolAddress(&p, g_off_pp); int* off_pp = (int*)p;
    cudaGetSymbolAddress(&p, g_off_ap); int* off_ap = (int*)p;
    cudaGetSymbolAddress(&p, g_off_pa); int* off_pa = (int*)p;
    cudaGetSymbolAddress(&p, g_srt);    int* srt    = (int*)p;
    cudaGetSymbolAddress(&p, g_writer); int* writer = (int*)p;

    int* srt_pp = srt;
    int* srt_ap = srt + EPP;
    int* srt_pa = srt + EPP + EAP;

    float* ed0 = ed;
    float* ed1 = ed + NP * 4;
    float* ed2 = ed + 2 * NP * 4;

    const int TB = 256;
    auto blocks = [](long long n) { return (int)((n + 255) / 256); };

    // ---- CSR build (3 relations; reused by both layers) ----
    auto build_csr = [&](const int* src, const int* dst, int E, int* off, int Nd, int* s) {
        zero_int<<<blocks(Nd + 1), TB>>>(off, Nd + 1);
        count_kernel<<<blocks(E), TB>>>(dst, off, E);
        scan_writer<<<1, 1024>>>(off, writer, Nd + 1, Nd);
        scatter_kernel<<<blocks(E), TB>>>(src, dst, writer, s, E);
    };
    build_csr(src_pp, dst_pp, EPP, off_pp, NP, srt_pp);
    build_csr(src_ap, dst_ap, EAP, off_ap, NP, srt_ap);
    build_csr(src_pa, dst_pa, EPA, off_pa, NA, srt_pa);

    compute_vd<<<blocks(2 * 3 * 128 * 4), TB>>>(Wdst1, adst1, Wdst2, adst2, vd1, vd2);

    auto gemm = [&](const float* xs, int Ns, const float* Ws, const float* a_s, int D) {
        dim3 grid(D / 64, (Ns + BM - 1) / BM);
        if (D == 128)
            sgemm_es<32><<<grid, 256>>>(xs, Ws, hs, es, a_s, Ns, D);
        else
            sgemm_es<16><<<grid, 256>>>(xs, Ws, hs, es, a_s, Ns, D);
    };
    auto gather = [&](const int* off, const int* s, float* edr, float* acc,
                      int Nd, int D, int add, const float* bias0,
                      const float* bias1, int relu) {
        int nthreads = Nd * 32;
        if (D == 128)
            gat_gather<128><<<blocks(nthreads), TB>>>(off, s, es, edr, hs, acc,
                                                      Nd, add, bias0, bias1, relu);
        else
            gat_gather<64><<<blocks(nthreads), TB>>>(off, s, es, edr, hs, acc,
                                                     Nd, add, bias0, bias1, relu);
    };

    // ---------------- layer 1 (D=128) ----------------
    ed_nodes2<<<blocks(NP), TB>>>(x_p, vd1 + 0 * 512, vd1 + 1 * 512, ed0, ed1, NP);
    ed_nodes1<<<blocks(NA), TB>>>(x_a, vd1 + 2 * 512, ed2, NA);

    gemm(x_p, NP, Wsrc1 + 0 * 128 * 128, asrc1 + 0 * 128, 128);
    gather(off_pp, srt_pp, ed0, accp, NP, 128, 0, nullptr, nullptr, 0);

    gemm(x_a, NA, Wsrc1 + 1 * 128 * 128, asrc1 + 1 * 128, 128);
    gather(off_ap, srt_ap, ed1, accp, NP, 128, 1, b1 + 0, b1 + 128, 1);

    gemm(x_p, NP, Wsrc1 + 2 * 128 * 128, asrc1 + 2 * 128, 128);
    gather(off_pa, srt_pa, ed2, acca, NA, 128, 0, b1 + 256, nullptr, 1);

    // ---------------- layer 2 (D=64) -> d_out ----------------
    ed_nodes2<<<blocks(NP), TB>>>(accp, vd2 + 0 * 512, vd2 + 1 * 512, ed0, ed1, NP);
    ed_nodes1<<<blocks(NA), TB>>>(acca, vd2 + 2 * 512, ed2, NA);

    gemm(accp, NP, Wsrc2 + 0 * 128 * 64, asrc2 + 0 * 64, 64);
    gather(off_pp, srt_pp, ed0, out, NP, 64, 0, nullptr, nullptr, 0);

    gemm(acca, NA, Wsrc2 + 1 * 128 * 64, asrc2 + 1 * 64, 64);
    gather(off_ap, srt_ap, ed1, out, NP, 64, 1, b2 + 0, b2 + 64, 0);

    gemm(accp, NP, Wsrc2 + 2 * 128 * 64, asrc2 + 2 * 64, 64);
    gather(off_pa, srt_pa, ed2, out + (size_t)NP * 64, NA, 64, 0, b2 + 128, nullptr, 0);
}

// round 9
// speedup vs baseline: 1.9097x; 1.9097x over previous
#include <cuda_runtime.h>
#include <cuda_bf16.h>
#include <cuda_fp16.h>
#include <cstdint>

#define NP 100000
#define NA 50000
#define EPP 1600000
#define EAP 800000
#define EPA 800000

// ---------------- scratch ----------------------------------------------------
__device__ __align__(16) __half g_hs[NP * 128];    // transformed src feats (fp16)
__device__ __align__(16) float g_es[NP * 4];
__device__ __align__(16) float g_ed[3 * NP * 4];
__device__ __align__(16) float g_accp[NP * 128];
__device__ __align__(16) float g_acca[NA * 128];
__device__ __align__(16) float g_vd1[3 * 128 * 4];
__device__ __align__(16) float g_vd2[3 * 128 * 4];
// CSR scratch
__device__ int g_off_pp[NP + 1];
__device__ int g_off_ap[NP + 1];
__device__ int g_off_pa[NA + 1];
__device__ int g_srt[EPP + EAP + EPA];
__device__ int g_writer[NP];

// ---------------- helpers ----------------------------------------------------
__device__ __forceinline__ float lrelu(float x) { return x > 0.f ? x : 0.2f * x; }

__device__ __forceinline__ unsigned long long pack2(float lo, float hi) {
    unsigned long long r;
    asm("mov.b64 %0, {%1, %2};" : "=l"(r) : "f"(lo), "f"(hi));
    return r;
}
__device__ __forceinline__ void fma2(unsigned long long& d,
                                     unsigned long long a, unsigned long long b) {
    asm("fma.rn.f32x2 %0, %1, %2, %0;" : "+l"(d) : "l"(a), "l"(b));
}
__device__ __forceinline__ float2 unpack2(unsigned long long v) {
    float lo, hi;
    asm("mov.b64 {%0, %1}, %2;" : "=f"(lo), "=f"(hi) : "l"(v));
    return make_float2(lo, hi);
}

// ---------------- CSR build kernels -------------------------------------------
__global__ void zero_int(int* __restrict__ p, int n) {
    int i = blockIdx.x * blockDim.x + threadIdx.x;
    if (i < n) p[i] = 0;
}
__global__ void count_kernel(const int* __restrict__ dst, int* __restrict__ off, int E) {
    int e = blockIdx.x * blockDim.x + threadIdx.x;
    if (e < E) atomicAdd(&off[dst[e] + 1], 1);
}
__global__ void __launch_bounds__(1024)
scan_writer(int* __restrict__ off, int* __restrict__ writer, int n, int nw) {
    __shared__ int ssum[1024];
    int tid = threadIdx.x;
    int running = 0;
    for (int base = 0; base < n; base += 4096) {
        int idx = base + tid * 4;
        int v0 = idx + 0 < n ? off[idx + 0] : 0;
        int v1 = idx + 1 < n ? off[idx + 1] : 0;
        int v2 = idx + 2 < n ? off[idx + 2] : 0;
        int v3 = idx + 3 < n ? off[idx + 3] : 0;
        int p0 = v0, p1 = p0 + v1, p2 = p1 + v2, p3 = p2 + v3;
        ssum[tid] = p3;
        __syncthreads();
        for (int o = 1; o < 1024; o <<= 1) {
            int val = 0;
            if (tid >= o) val = ssum[tid - o];
            __syncthreads();
            if (tid >= o) ssum[tid] += val;
            __syncthreads();
        }
        int excl = running + (tid ? ssum[tid - 1] : 0);
        int total = ssum[1023];
        __syncthreads();
        int s0 = excl + p0, s1 = excl + p1, s2 = excl + p2, s3 = excl + p3;
        if (idx + 0 < n) { off[idx + 0] = s0; if (idx + 0 < nw) writer[idx + 0] = s0; }
        if (idx + 1 < n) { off[idx + 1] = s1; if (idx + 1 < nw) writer[idx + 1] = s1; }
        if (idx + 2 < n) { off[idx + 2] = s2; if (idx + 2 < nw) writer[idx + 2] = s2; }
        if (idx + 3 < n) { off[idx + 3] = s3; if (idx + 3 < nw) writer[idx + 3] = s3; }
        running += total;
    }
}
__global__ void scatter_kernel(const int* __restrict__ src, const int* __restrict__ dst,
                               int* __restrict__ writer, int* __restrict__ srt, int E) {
    int e = blockIdx.x * blockDim.x + threadIdx.x;
    if (e >= E) return;
    int pos = atomicAdd(&writer[dst[e]], 1);
    srt[pos] = src[e];
}

// ---------------- SGEMM (f32x2) + fused es epilogue, fp16 C output ------------
#define BM 128
#define BN 64
#define BK 16
template <int CC>
__global__ void __launch_bounds__(256)
sgemm_es(const float* __restrict__ A, const float* __restrict__ B,
         __half* __restrict__ C, float* __restrict__ es,
         const float* __restrict__ a_s, int M, int N) {
    const int K = 128;
    __shared__ float As[2][BK][BM + 4];
    __shared__ float Bs[2][BK][BN];
    int tid = threadIdx.x;
    int m0 = blockIdx.y * BM, n0 = blockIdx.x * BN;

    int aRow = tid >> 1;
    int aC4 = (tid & 1) * 2;
    int bK = tid >> 4;
    int bC4 = tid & 15;
    int ty = tid >> 4;
    int tx = tid & 15;

    unsigned long long acc2[4][4];
#pragma unroll
    for (int ip = 0; ip < 4; ip++)
#pragma unroll
        for (int j = 0; j < 4; j++) acc2[ip][j] = 0ull;

    float4 ra0, ra1, rb;
    auto loadg = [&](int k0) {
        int m = m0 + aRow;
        if (m < M) {
            ra0 = *(const float4*)(A + (size_t)m * K + k0 + aC4 * 4);
            ra1 = *(const float4*)(A + (size_t)m * K + k0 + aC4 * 4 + 4);
        } else {
            ra0 = make_float4(0.f, 0.f, 0.f, 0.f);
            ra1 = ra0;
        }
        rb = *(const float4*)(B + (size_t)(k0 + bK) * N + n0 + bC4 * 4);
    };
    auto stores = [&](int buf) {
        As[buf][aC4 * 4 + 0][aRow] = ra0.x;
        As[buf][aC4 * 4 + 1][aRow] = ra0.y;
        As[buf][aC4 * 4 + 2][aRow] = ra0.z;
        As[buf][aC4 * 4 + 3][aRow] = ra0.w;
        As[buf][aC4 * 4 + 4][aRow] = ra1.x;
        As[buf][aC4 * 4 + 5][aRow] = ra1.y;
        As[buf][aC4 * 4 + 6][aRow] = ra1.z;
        As[buf][aC4 * 4 + 7][aRow] = ra1.w;
        *(float4*)&Bs[buf][bK][bC4 * 4] = rb;
    };

    loadg(0);
    stores(0);
    __syncthreads();

    const int NCH = K / BK;
#pragma unroll
    for (int c = 0; c < NCH; c++) {
        if (c + 1 < NCH) loadg((c + 1) * BK);
        int buf = c & 1;
#pragma unroll
        for (int k = 0; k < BK; k++) {
            float4 a0 = *(const float4*)&As[buf][k][ty * 8];
            float4 a1 = *(const float4*)&As[buf][k][ty * 8 + 4];
            float4 b = *(const float4*)&Bs[buf][k][tx * 4];
            unsigned long long ap[4] = {pack2(a0.x, a0.y), pack2(a0.z, a0.w),
                                        pack2(a1.x, a1.y), pack2(a1.z, a1.w)};
            unsigned long long bb[4] = {pack2(b.x, b.x), pack2(b.y, b.y),
                                        pack2(b.z, b.z), pack2(b.w, b.w)};
#pragma unroll
            for (int ip = 0; ip < 4; ip++)
#pragma unroll
                for (int j = 0; j < 4; j++) fma2(acc2[ip][j], ap[ip], bb[j]);
        }
        if (c + 1 < NCH) stores((c + 1) & 1);
        __syncthreads();
    }

    float accf[8][4];
#pragma unroll
    for (int ip = 0; ip < 4; ip++)
#pragma unroll
        for (int j = 0; j < 4; j++) {
            float2 v = unpack2(acc2[ip][j]);
            accf[2 * ip + 0][j] = v.x;
            accf[2 * ip + 1][j] = v.y;
        }

    {
        constexpr int RW = CC / 4;
        float4 a4 = *(const float4*)(a_s + n0 + tx * 4);
        int h = (n0 + tx * 4) / CC;
#pragma unroll
        for (int i = 0; i < 8; i++) {
            float pv = accf[i][0] * a4.x + accf[i][1] * a4.y +
                       accf[i][2] * a4.z + accf[i][3] * a4.w;
#pragma unroll
            for (int off = RW / 2; off > 0; off >>= 1)
                pv += __shfl_down_sync(0xffffffffu, pv, off, RW);
            int m = m0 + ty * 8 + i;
            if (m < M && (tx & (RW - 1)) == 0) es[m * 4 + h] = pv;
        }
    }

#pragma unroll
    for (int i = 0; i < 8; i++) {
        int m = m0 + ty * 8 + i;
        if (m < M) {
            union { __half2 h[2]; uint2 u; } cv;
            cv.h[0] = __floats2half2_rn(accf[i][0], accf[i][1]);
            cv.h[1] = __floats2half2_rn(accf[i][2], accf[i][3]);
            *(uint2*)(C + (size_t)m * N + n0 + tx * 4) = cv.u;
        }
    }
}

// ---------------- vd folding ---------------------------------------------------
__global__ void compute_vd(const float* __restrict__ Wd1, const float* __restrict__ ad1,
                           const float* __restrict__ Wd2, const float* __restrict__ ad2,
                           float* __restrict__ vd1, float* __restrict__ vd2) {
    int i = blockIdx.x * blockDim.x + threadIdx.x;
    if (i >= 2 * 3 * 128 * 4) return;
    int layer = i >= 3 * 128 * 4;
    int ii = i - layer * 3 * 128 * 4;
    int h = ii & 3;
    int f = (ii >> 2) & 127;
    int r = ii >> 9;
    int D = layer ? 64 : 128;
    int C = D / 4;
    const float* W = (layer ? Wd2 : Wd1) + (size_t)r * 128 * D + (size_t)f * D + h * C;
    const float* a = (layer ? ad2 : ad1) + r * 4 * C + h * C;
    float s = 0.f;
    for (int c = 0; c < C; c++) s += W[c] * a[c];
    (layer ? vd2 : vd1)[r * 512 + f * 4 + h] = s;
}

// -------- ed, thread-per-node, TWO relations, smem vd, f32x2 -------------------
__global__ void __launch_bounds__(256)
ed_nodes2(const float* __restrict__ x,
          const float* __restrict__ vdA, const float* __restrict__ vdB,
          float* __restrict__ edA, float* __restrict__ edB, int N) {
    __shared__ __align__(16) float sv[1024];
    int t = threadIdx.x;
    ((float4*)sv)[t] = (t < 128) ? ((const float4*)vdA)[t]
                                 : ((const float4*)vdB)[t - 128];
    __syncthreads();
    int n = blockIdx.x * blockDim.x + t;
    if (n >= N) return;
    unsigned long long accA[2] = {0ull, 0ull}, accB[2] = {0ull, 0ull};
    const float4* xr = (const float4*)(x + (size_t)n * 128);
#pragma unroll 8
    for (int r = 0; r < 32; r++) {
        float4 xv = xr[r];
#pragma unroll
        for (int j = 0; j < 4; j++) {
            float xs = j == 0 ? xv.x : j == 1 ? xv.y : j == 2 ? xv.z : xv.w;
            unsigned long long xp = pack2(xs, xs);
            ulonglong2 va = *(const ulonglong2*)&sv[(4 * r + j) * 4];
            fma2(accA[0], xp, va.x);
            fma2(accA[1], xp, va.y);
            ulonglong2 vb = *(const ulonglong2*)&sv[512 + (4 * r + j) * 4];
            fma2(accB[0], xp, vb.x);
            fma2(accB[1], xp, vb.y);
        }
    }
    float2 a0 = unpack2(accA[0]), a1 = unpack2(accA[1]);
    float2 b0 = unpack2(accB[0]), b1 = unpack2(accB[1]);
    ((float4*)edA)[n] = make_float4(a0.x, a0.y, a1.x, a1.y);
    ((float4*)edB)[n] = make_float4(b0.x, b0.y, b1.x, b1.y);
}

__global__ void __launch_bounds__(256)
ed_nodes1(const float* __restrict__ x, const float* __restrict__ vd,
          float* __restrict__ ed, int N) {
    __shared__ __align__(16) float sv[512];
    int t = threadIdx.x;
    if (t < 128) ((float4*)sv)[t] = ((const float4*)vd)[t];
    __syncthreads();
    int n = blockIdx.x * blockDim.x + t;
    if (n >= N) return;
    unsigned long long acc[2] = {0ull, 0ull};
    const float4* xr = (const float4*)(x + (size_t)n * 128);
#pragma unroll 8
    for (int r = 0; r < 32; r++) {
        float4 xv = xr[r];
#pragma unroll
        for (int j = 0; j < 4; j++) {
            float xs = j == 0 ? xv.x : j == 1 ? xv.y : j == 2 ? xv.z : xv.w;
            unsigned long long xp = pack2(xs, xs);
            ulonglong2 va = *(const ulonglong2*)&sv[(4 * r + j) * 4];
            fma2(acc[0], xp, va.x);
            fma2(acc[1], xp, va.y);
        }
    }
    float2 a0 = unpack2(acc[0]), a1 = unpack2(acc[1]);
    ((float4*)ed)[n] = make_float4(a0.x, a0.y, a1.x, a1.y);
}

// -------- GATHER conv: warp/dst; lanes iterate ALL edges independently ---------
// No shuffles. Lane owns CPL channels of one head; den accumulated per-lane.
template <int D>
__global__ void __launch_bounds__(256)
gat_gather(const int* __restrict__ off, const int* __restrict__ srt,
           const float* __restrict__ es, const float* __restrict__ ed,
           const __half* __restrict__ hs, float* __restrict__ acc,
           int Nd, int add, const float* __restrict__ bias0,
           const float* __restrict__ bias1, int relu) {
    constexpr int CPL = D / 32;            // 4 or 2 channels per lane
    int warp = (blockIdx.x * blockDim.x + threadIdx.x) >> 5;
    int lane = threadIdx.x & 31;
    if (warp >= Nd) return;
    int d = warp;
    int start = __ldg(&off[d]), end = __ldg(&off[d + 1]);
    int h = lane >> 3;                     // head (both configs)
    float edh = __ldg(&ed[d * 4 + h]);
    float den = 0.f;
    float a0 = 0.f, a1 = 0.f, a2 = 0.f, a3 = 0.f;

    int i = start;
    // unrolled-by-2 main loop for MLP
    for (; i + 2 <= end; i += 2) {
        int s0 = __ldg(&srt[i]);
        int s1 = __ldg(&srt[i + 1]);
        float q0 = __ldg(&es[s0 * 4 + h]);
        float q1 = __ldg(&es[s1 * 4 + h]);
        uint2 u0, u1;
        unsigned w0, w1;
        if (D == 128) {
            u0 = *(const uint2*)(hs + (size_t)s0 * D + lane * 4);
            u1 = *(const uint2*)(hs + (size_t)s1 * D + lane * 4);
        } else {
            w0 = *(const unsigned*)(hs + (size_t)s0 * D + lane * 2);
            w1 = *(const unsigned*)(hs + (size_t)s1 * D + lane * 2);
        }
        float ee0 = __expf(lrelu(q0 + edh));
        float ee1 = __expf(lrelu(q1 + edh));
        den += ee0 + ee1;
        if (D == 128) {
            union { uint2 u; __half2 h2[2]; } c0, c1;
            c0.u = u0; c1.u = u1;
            float2 p00 = __half22float2(c0.h2[0]), p01 = __half22float2(c0.h2[1]);
            float2 p10 = __half22float2(c1.h2[0]), p11 = __half22float2(c1.h2[1]);
            a0 += ee0 * p00.x + ee1 * p10.x;
            a1 += ee0 * p00.y + ee1 * p10.y;
            a2 += ee0 * p01.x + ee1 * p11.x;
            a3 += ee0 * p01.y + ee1 * p11.y;
        } else {
            union { unsigned u; __half2 h2; } c0, c1;
            c0.u = w0; c1.u = w1;
            float2 p0 = __half22float2(c0.h2), p1 = __half22float2(c1.h2);
            a0 += ee0 * p0.x + ee1 * p1.x;
            a1 += ee0 * p0.y + ee1 * p1.y;
        }
    }
    for (; i < end; i++) {
        int s = __ldg(&srt[i]);
        float ee = __expf(lrelu(__ldg(&es[s * 4 + h]) + edh));
        den += ee;
        if (D == 128) {
            union { uint2 u; __half2 h2[2]; } cv;
            cv.u = *(const uint2*)(hs + (size_t)s * D + lane * 4);
            float2 p0 = __half22float2(cv.h2[0]), p1 = __half22float2(cv.h2[1]);
            a0 += ee * p0.x; a1 += ee * p0.y; a2 += ee * p1.x; a3 += ee * p1.y;
        } else {
            union { unsigned u; __half2 h2; } cv;
            cv.u = *(const unsigned*)(hs + (size_t)s * D + lane * 2);
            float2 p = __half22float2(cv.h2);
            a0 += ee * p.x; a1 += ee * p.y;
        }
    }

    float inv = 1.f / (den + 1e-16f);
    int cb = lane * CPL;
    float* dp = acc + (size_t)d * D + cb;
    if (D == 128) {
        float4 o = make_float4(a0 * inv, a1 * inv, a2 * inv, a3 * inv);
        if (add) {
            float4 pa = *(const float4*)dp;
            o.x += pa.x; o.y += pa.y; o.z += pa.z; o.w += pa.w;
        }
        if (bias0) {
            float4 b = *(const float4*)(bias0 + cb);
            o.x += b.x; o.y += b.y; o.z += b.z; o.w += b.w;
        }
        if (bias1) {
            float4 b = *(const float4*)(bias1 + cb);
            o.x += b.x; o.y += b.y; o.z += b.z; o.w += b.w;
        }
        if (relu) {
            o.x = fmaxf(o.x, 0.f); o.y = fmaxf(o.y, 0.f);
            o.z = fmaxf(o.z, 0.f); o.w = fmaxf(o.w, 0.f);
        }
        *(float4*)dp = o;
    } else {
        float2 o = make_float2(a0 * inv, a1 * inv);
        if (add) {
            float2 pa = *(const float2*)dp;
            o.x += pa.x; o.y += pa.y;
        }
        if (bias0) {
            float2 b = *(const float2*)(bias0 + cb);
            o.x += b.x; o.y += b.y;
        }
        if (bias1) {
            float2 b = *(const float2*)(bias1 + cb);
            o.x += b.x; o.y += b.y;
        }
        if (relu) {
            o.x = fmaxf(o.x, 0.f); o.y = fmaxf(o.y, 0.f);
        }
        *(float2*)dp = o;
    }
}

// =============================================================================
extern "C" void kernel_launch(void* const* d_in, const int* in_sizes, int n_in,
                              void* d_out, int out_size) {
    const float* x_p = (const float*)d_in[0];
    const float* x_a = (const float*)d_in[1];
    const int* src_pp = (const int*)d_in[2];
    const int* dst_pp = (const int*)d_in[3];
    const int* src_ap = (const int*)d_in[4];
    const int* dst_ap = (const int*)d_in[5];
    const int* src_pa = (const int*)d_in[6];
    const int* dst_pa = (const int*)d_in[7];
    const float* Wsrc1 = (const float*)d_in[8];
    const float* Wdst1 = (const float*)d_in[9];
    const float* asrc1 = (const float*)d_in[10];
    const float* adst1 = (const float*)d_in[11];
    const float* b1 = (const float*)d_in[12];
    const float* Wsrc2 = (const float*)d_in[13];
    const float* Wdst2 = (const float*)d_in[14];
    const float* asrc2 = (const float*)d_in[15];
    const float* adst2 = (const float*)d_in[16];
    const float* b2 = (const float*)d_in[17];
    float* out = (float*)d_out;

    void* p;
    cudaGetSymbolAddress(&p, g_hs);     __half* hs  = (__half*)p;
    cudaGetSymbolAddress(&p, g_es);     float* es   = (float*)p;
    cudaGetSymbolAddress(&p, g_ed);     float* ed   = (float*)p;
    cudaGetSymbolAddress(&p, g_accp);   float* accp = (float*)p;
    cudaGetSymbolAddress(&p, g_acca);   float* acca = (float*)p;
    cudaGetSymbolAddress(&p, g_vd1);    float* vd1  = (float*)p;
    cudaGetSymbolAddress(&p, g_vd2);    float* vd2  = (float*)p;
    cudaGetSymbolAddress(&p, g_off_pp); int* off_pp = (int*)p;
    cudaGetSymbolAddress(&p, g_off_ap); int* off_ap = (int*)p;
    cudaGetSymbolAddress(&p, g_off_pa); int* off_pa = (int*)p;
    cudaGetSymbolAddress(&p, g_srt);    int* srt    = (int*)p;
    cudaGetSymbolAddress(&p, g_writer); int* writer = (int*)p;

    int* srt_pp = srt;
    int* srt_ap = srt + EPP;
    int* srt_pa = srt + EPP + EAP;

    float* ed0 = ed;
    float* ed1 = ed + NP * 4;
    float* ed2 = ed + 2 * NP * 4;

    const int TB = 256;
    auto blocks = [](long long n) { return (int)((n + 255) / 256); };

    auto build_csr = [&](const int* src, const int* dst, int E, int* off, int Nd, int* s) {
        zero_int<<<blocks(Nd + 1), TB>>>(off, Nd + 1);
        count_kernel<<<blocks(E), TB>>>(dst, off, E);
        scan_writer<<<1, 1024>>>(off, writer, Nd + 1, Nd);
        scatter_kernel<<<blocks(E), TB>>>(src, dst, writer, s, E);
    };
    build_csr(src_pp, dst_pp, EPP, off_pp, NP, srt_pp);
    build_csr(src_ap, dst_ap, EAP, off_ap, NP, srt_ap);
    build_csr(src_pa, dst_pa, EPA, off_pa, NA, srt_pa);

    compute_vd<<<blocks(2 * 3 * 128 * 4), TB>>>(Wdst1, adst1, Wdst2, adst2, vd1, vd2);

    auto gemm = [&](const float* xs, int Ns, const float* Ws, const float* a_s, int D) {
        dim3 grid(D / 64, (Ns + BM - 1) / BM);
        if (D == 128)
            sgemm_es<32><<<grid, 256>>>(xs, Ws, hs, es, a_s, Ns, D);
        else
            sgemm_es<16><<<grid, 256>>>(xs, Ws, hs, es, a_s, Ns, D);
    };
    auto gather = [&](const int* off, const int* s, float* edr, float* acc,
                      int Nd, int D, int add, const float* bias0,
                      const float* bias1, int relu) {
        int nthreads = Nd * 32;
        if (D == 128)
            gat_gather<128><<<blocks(nthreads), TB>>>(off, s, es, edr, hs, acc,
                                                      Nd, add, bias0, bias1, relu);
        else
            gat_gather<64><<<blocks(nthreads), TB>>>(off, s, es, edr, hs, acc,
                                                     Nd, add, bias0, bias1, relu);
    };

    // ---------------- layer 1 (D=128) ----------------
    ed_nodes2<<<blocks(NP), TB>>>(x_p, vd1 + 0 * 512, vd1 + 1 * 512, ed0, ed1, NP);
    ed_nodes1<<<blocks(NA), TB>>>(x_a, vd1 + 2 * 512, ed2, NA);

    gemm(x_p, NP, Wsrc1 + 0 * 128 * 128, asrc1 + 0 * 128, 128);
    gather(off_pp, srt_pp, ed0, accp, NP, 128, 0, nullptr, nullptr, 0);

    gemm(x_a, NA, Wsrc1 + 1 * 128 * 128, asrc1 + 1 * 128, 128);
    gather(off_ap, srt_ap, ed1, accp, NP, 128, 1, b1 + 0, b1 + 128, 1);

    gemm(x_p, NP, Wsrc1 + 2 * 128 * 128, asrc1 + 2 * 128, 128);
    gather(off_pa, srt_pa, ed2, acca, NA, 128, 0, b1 + 256, nullptr, 1);

    // ---------------- layer 2 (D=64) -> d_out ----------------
    ed_nodes2<<<blocks(NP), TB>>>(accp, vd2 + 0 * 512, vd2 + 1 * 512, ed0, ed1, NP);
    ed_nodes1<<<blocks(NA), TB>>>(acca, vd2 + 2 * 512, ed2, NA);

    gemm(accp, NP, Wsrc2 + 0 * 128 * 64, asrc2 + 0 * 64, 64);
    gather(off_pp, srt_pp, ed0, out, NP, 64, 0, nullptr, nullptr, 0);

    gemm(acca, NA, Wsrc2 + 1 * 128 * 64, asrc2 + 1 * 64, 64);
    gather(off_ap, srt_ap, ed1, out, NP, 64, 1, b2 + 0, b2 + 64, 0);

    gemm(accp, NP, Wsrc2 + 2 * 128 * 64, asrc2 + 2 * 64, 64);
    gather(off_pa, srt_pa, ed2, out + (size_t)NP * 64, NA, 64, 0, b2 + 128, nullptr, 0);
}

// round 10
// speedup vs baseline: 2.3026x; 1.2057x over previous
#include <cuda_runtime.h>
#include <cuda_bf16.h>
#include <cuda_fp16.h>
#include <cstdint>

#define NP 100000
#define NA 50000
#define EPP 1600000
#define EAP 800000
#define EPA 800000

// ---------------- scratch ----------------------------------------------------
__device__ __align__(16) __half g_hs[NP * 128];    // transformed src feats (fp16)
__device__ __align__(16) float g_es[NP * 8];       // per src node/head: (e^x, e^{0.2x})
__device__ __align__(16) float g_ed[3 * NP * 8];   // per relation dst node/head pairs
__device__ __align__(16) float g_accp[NP * 128];
__device__ __align__(16) float g_acca[NA * 128];
__device__ __align__(16) float g_vd1[3 * 128 * 4];
__device__ __align__(16) float g_vd2[3 * 128 * 4];
// CSR scratch
__device__ int g_off_pp[NP + 1];
__device__ int g_off_ap[NP + 1];
__device__ int g_off_pa[NA + 1];
__device__ int g_srt[EPP + EAP + EPA];
__device__ int g_writer[NP + NP + NA];

// ---------------- helpers ----------------------------------------------------
__device__ __forceinline__ unsigned long long pack2(float lo, float hi) {
    unsigned long long r;
    asm("mov.b64 %0, {%1, %2};" : "=l"(r) : "f"(lo), "f"(hi));
    return r;
}
__device__ __forceinline__ void fma2(unsigned long long& d,
                                     unsigned long long a, unsigned long long b) {
    asm("fma.rn.f32x2 %0, %1, %2, %0;" : "+l"(d) : "l"(a), "l"(b));
}
__device__ __forceinline__ float2 unpack2(unsigned long long v) {
    float lo, hi;
    asm("mov.b64 {%0, %1}, %2;" : "=f"(lo), "=f"(hi) : "l"(v));
    return make_float2(lo, hi);
}

// ---------------- batched CSR build -------------------------------------------
__global__ void zero3(int* __restrict__ a, int na, int* __restrict__ b, int nb,
                      int* __restrict__ c, int nc) {
    int i = blockIdx.x * blockDim.x + threadIdx.x;
    if (i < na) a[i] = 0;
    else if (i < na + nb) b[i - na] = 0;
    else if (i < na + nb + nc) c[i - na - nb] = 0;
}
__global__ void count3(const int* __restrict__ d0, const int* __restrict__ d1,
                       const int* __restrict__ d2, int* __restrict__ o0,
                       int* __restrict__ o1, int* __restrict__ o2) {
    int i = blockIdx.x * blockDim.x + threadIdx.x;
    if (i < EPP) atomicAdd(&o0[d0[i] + 1], 1);
    else if (i < EPP + EAP) atomicAdd(&o1[d1[i - EPP] + 1], 1);
    else if (i < EPP + EAP + EPA) atomicAdd(&o2[d2[i - EPP - EAP] + 1], 1);
}
__device__ void scan_one(int* __restrict__ off, int* __restrict__ writer, int n, int nw) {
    __shared__ int ssum[1024];
    int tid = threadIdx.x;
    int running = 0;
    for (int base = 0; base < n; base += 4096) {
        int idx = base + tid * 4;
        int v0 = idx + 0 < n ? off[idx + 0] : 0;
        int v1 = idx + 1 < n ? off[idx + 1] : 0;
        int v2 = idx + 2 < n ? off[idx + 2] : 0;
        int v3 = idx + 3 < n ? off[idx + 3] : 0;
        int p0 = v0, p1 = p0 + v1, p2 = p1 + v2, p3 = p2 + v3;
        ssum[tid] = p3;
        __syncthreads();
        for (int o = 1; o < 1024; o <<= 1) {
            int val = 0;
            if (tid >= o) val = ssum[tid - o];
            __syncthreads();
            if (tid >= o) ssum[tid] += val;
            __syncthreads();
        }
        int excl = running + (tid ? ssum[tid - 1] : 0);
        int total = ssum[1023];
        __syncthreads();
        int s0 = excl + p0, s1 = excl + p1, s2 = excl + p2, s3 = excl + p3;
        if (idx + 0 < n) { off[idx + 0] = s0; if (idx + 0 < nw) writer[idx + 0] = s0; }
        if (idx + 1 < n) { off[idx + 1] = s1; if (idx + 1 < nw) writer[idx + 1] = s1; }
        if (idx + 2 < n) { off[idx + 2] = s2; if (idx + 2 < nw) writer[idx + 2] = s2; }
        if (idx + 3 < n) { off[idx + 3] = s3; if (idx + 3 < nw) writer[idx + 3] = s3; }
        running += total;
    }
}
__global__ void __launch_bounds__(1024)
scan3(int* __restrict__ o0, int* __restrict__ o1, int* __restrict__ o2,
      int* __restrict__ writer) {
    if (blockIdx.x == 0)      scan_one(o0, writer, NP + 1, NP);
    else if (blockIdx.x == 1) scan_one(o1, writer + NP, NP + 1, NP);
    else                      scan_one(o2, writer + 2 * NP, NA + 1, NA);
}
__global__ void scatter3(const int* __restrict__ s0, const int* __restrict__ d0,
                         const int* __restrict__ s1, const int* __restrict__ d1,
                         const int* __restrict__ s2, const int* __restrict__ d2,
                         int* __restrict__ writer, int* __restrict__ srt) {
    int i = blockIdx.x * blockDim.x + threadIdx.x;
    if (i < EPP) {
        int pos = atomicAdd(&writer[d0[i]], 1);
        srt[pos] = s0[i];
    } else if (i < EPP + EAP) {
        int e = i - EPP;
        int pos = atomicAdd(&writer[NP + d1[e]], 1);
        srt[EPP + pos] = s1[e];
    } else if (i < EPP + EAP + EPA) {
        int e = i - EPP - EAP;
        int pos = atomicAdd(&writer[2 * NP + d2[e]], 1);
        srt[EPP + EAP + pos] = s2[e];
    }
}

// ---------------- SGEMM (f32x2) + fused exp-pair es epilogue, fp16 C ----------
#define BM 128
#define BN 64
#define BK 16
template <int CC>
__global__ void __launch_bounds__(256)
sgemm_es(const float* __restrict__ A, const float* __restrict__ B,
         __half* __restrict__ C, float* __restrict__ es,
         const float* __restrict__ a_s, int M, int N) {
    const int K = 128;
    __shared__ float As[2][BK][BM + 4];
    __shared__ float Bs[2][BK][BN];
    int tid = threadIdx.x;
    int m0 = blockIdx.y * BM, n0 = blockIdx.x * BN;

    int aRow = tid >> 1;
    int aC4 = (tid & 1) * 2;
    int bK = tid >> 4;
    int bC4 = tid & 15;
    int ty = tid >> 4;
    int tx = tid & 15;

    unsigned long long acc2[4][4];
#pragma unroll
    for (int ip = 0; ip < 4; ip++)
#pragma unroll
        for (int j = 0; j < 4; j++) acc2[ip][j] = 0ull;

    float4 ra0, ra1, rb;
    auto loadg = [&](int k0) {
        int m = m0 + aRow;
        if (m < M) {
            ra0 = *(const float4*)(A + (size_t)m * K + k0 + aC4 * 4);
            ra1 = *(const float4*)(A + (size_t)m * K + k0 + aC4 * 4 + 4);
        } else {
            ra0 = make_float4(0.f, 0.f, 0.f, 0.f);
            ra1 = ra0;
        }
        rb = *(const float4*)(B + (size_t)(k0 + bK) * N + n0 + bC4 * 4);
    };
    auto stores = [&](int buf) {
        As[buf][aC4 * 4 + 0][aRow] = ra0.x;
        As[buf][aC4 * 4 + 1][aRow] = ra0.y;
        As[buf][aC4 * 4 + 2][aRow] = ra0.z;
        As[buf][aC4 * 4 + 3][aRow] = ra0.w;
        As[buf][aC4 * 4 + 4][aRow] = ra1.x;
        As[buf][aC4 * 4 + 5][aRow] = ra1.y;
        As[buf][aC4 * 4 + 6][aRow] = ra1.z;
        As[buf][aC4 * 4 + 7][aRow] = ra1.w;
        *(float4*)&Bs[buf][bK][bC4 * 4] = rb;
    };

    loadg(0);
    stores(0);
    __syncthreads();

    const int NCH = K / BK;
#pragma unroll
    for (int c = 0; c < NCH; c++) {
        if (c + 1 < NCH) loadg((c + 1) * BK);
        int buf = c & 1;
#pragma unroll
        for (int k = 0; k < BK; k++) {
            float4 a0 = *(const float4*)&As[buf][k][ty * 8];
            float4 a1 = *(const float4*)&As[buf][k][ty * 8 + 4];
            float4 b = *(const float4*)&Bs[buf][k][tx * 4];
            unsigned long long ap[4] = {pack2(a0.x, a0.y), pack2(a0.z, a0.w),
                                        pack2(a1.x, a1.y), pack2(a1.z, a1.w)};
            unsigned long long bb[4] = {pack2(b.x, b.x), pack2(b.y, b.y),
                                        pack2(b.z, b.z), pack2(b.w, b.w)};
#pragma unroll
            for (int ip = 0; ip < 4; ip++)
#pragma unroll
                for (int j = 0; j < 4; j++) fma2(acc2[ip][j], ap[ip], bb[j]);
        }
        if (c + 1 < NCH) stores((c + 1) & 1);
        __syncthreads();
    }

    float accf[8][4];
#pragma unroll
    for (int ip = 0; ip < 4; ip++)
#pragma unroll
        for (int j = 0; j < 4; j++) {
            float2 v = unpack2(acc2[ip][j]);
            accf[2 * ip + 0][j] = v.x;
            accf[2 * ip + 1][j] = v.y;
        }

    // es epilogue: write (e^x, e^{0.2x}) pair per node/head
    {
        constexpr int RW = CC / 4;
        float4 a4 = *(const float4*)(a_s + n0 + tx * 4);
        int h = (n0 + tx * 4) / CC;
#pragma unroll
        for (int i = 0; i < 8; i++) {
            float pv = accf[i][0] * a4.x + accf[i][1] * a4.y +
                       accf[i][2] * a4.z + accf[i][3] * a4.w;
#pragma unroll
            for (int off = RW / 2; off > 0; off >>= 1)
                pv += __shfl_down_sync(0xffffffffu, pv, off, RW);
            int m = m0 + ty * 8 + i;
            if (m < M && (tx & (RW - 1)) == 0)
                *(float2*)(es + m * 8 + h * 2) =
                    make_float2(__expf(pv), __expf(0.2f * pv));
        }
    }

#pragma unroll
    for (int i = 0; i < 8; i++) {
        int m = m0 + ty * 8 + i;
        if (m < M) {
            union { __half2 h[2]; uint2 u; } cv;
            cv.h[0] = __floats2half2_rn(accf[i][0], accf[i][1]);
            cv.h[1] = __floats2half2_rn(accf[i][2], accf[i][3]);
            *(uint2*)(C + (size_t)m * N + n0 + tx * 4) = cv.u;
        }
    }
}

// ---------------- vd folding ---------------------------------------------------
__global__ void compute_vd(const float* __restrict__ Wd1, const float* __restrict__ ad1,
                           const float* __restrict__ Wd2, const float* __restrict__ ad2,
                           float* __restrict__ vd1, float* __restrict__ vd2) {
    int i = blockIdx.x * blockDim.x + threadIdx.x;
    if (i >= 2 * 3 * 128 * 4) return;
    int layer = i >= 3 * 128 * 4;
    int ii = i - layer * 3 * 128 * 4;
    int h = ii & 3;
    int f = (ii >> 2) & 127;
    int r = ii >> 9;
    int D = layer ? 64 : 128;
    int C = D / 4;
    const float* W = (layer ? Wd2 : Wd1) + (size_t)r * 128 * D + (size_t)f * D + h * C;
    const float* a = (layer ? ad2 : ad1) + r * 4 * C + h * C;
    float s = 0.f;
    for (int c = 0; c < C; c++) s += W[c] * a[c];
    (layer ? vd2 : vd1)[r * 512 + f * 4 + h] = s;
}

// -------- ed, thread-per-node, TWO relations; writes exp pairs -----------------
__global__ void __launch_bounds__(256)
ed_nodes2(const float* __restrict__ x,
          const float* __restrict__ vdA, const float* __restrict__ vdB,
          float* __restrict__ edA, float* __restrict__ edB, int N) {
    __shared__ __align__(16) float sv[1024];
    int t = threadIdx.x;
    ((float4*)sv)[t] = (t < 128) ? ((const float4*)vdA)[t]
                                 : ((const float4*)vdB)[t - 128];
    __syncthreads();
    int n = blockIdx.x * blockDim.x + t;
    if (n >= N) return;
    unsigned long long accA[2] = {0ull, 0ull}, accB[2] = {0ull, 0ull};
    const float4* xr = (const float4*)(x + (size_t)n * 128);
#pragma unroll 8
    for (int r = 0; r < 32; r++) {
        float4 xv = xr[r];
#pragma unroll
        for (int j = 0; j < 4; j++) {
            float xs = j == 0 ? xv.x : j == 1 ? xv.y : j == 2 ? xv.z : xv.w;
            unsigned long long xp = pack2(xs, xs);
            ulonglong2 va = *(const ulonglong2*)&sv[(4 * r + j) * 4];
            fma2(accA[0], xp, va.x);
            fma2(accA[1], xp, va.y);
            ulonglong2 vb = *(const ulonglong2*)&sv[512 + (4 * r + j) * 4];
            fma2(accB[0], xp, vb.x);
            fma2(accB[1], xp, vb.y);
        }
    }
    float2 a0 = unpack2(accA[0]), a1 = unpack2(accA[1]);
    float2 b0 = unpack2(accB[0]), b1 = unpack2(accB[1]);
    ((float4*)edA)[n * 2 + 0] = make_float4(__expf(a0.x), __expf(0.2f * a0.x),
                                            __expf(a0.y), __expf(0.2f * a0.y));
    ((float4*)edA)[n * 2 + 1] = make_float4(__expf(a1.x), __expf(0.2f * a1.x),
                                            __expf(a1.y), __expf(0.2f * a1.y));
    ((float4*)edB)[n * 2 + 0] = make_float4(__expf(b0.x), __expf(0.2f * b0.x),
                                            __expf(b0.y), __expf(0.2f * b0.y));
    ((float4*)edB)[n * 2 + 1] = make_float4(__expf(b1.x), __expf(0.2f * b1.x),
                                            __expf(b1.y), __expf(0.2f * b1.y));
}

__global__ void __launch_bounds__(256)
ed_nodes1(const float* __restrict__ x, const float* __restrict__ vd,
          float* __restrict__ ed, int N) {
    __shared__ __align__(16) float sv[512];
    int t = threadIdx.x;
    if (t < 128) ((float4*)sv)[t] = ((const float4*)vd)[t];
    __syncthreads();
    int n = blockIdx.x * blockDim.x + t;
    if (n >= N) return;
    unsigned long long acc[2] = {0ull, 0ull};
    const float4* xr = (const float4*)(x + (size_t)n * 128);
#pragma unroll 8
    for (int r = 0; r < 32; r++) {
        float4 xv = xr[r];
#pragma unroll
        for (int j = 0; j < 4; j++) {
            float xs = j == 0 ? xv.x : j == 1 ? xv.y : j == 2 ? xv.z : xv.w;
            unsigned long long xp = pack2(xs, xs);
            ulonglong2 va = *(const ulonglong2*)&sv[(4 * r + j) * 4];
            fma2(acc[0], xp, va.x);
            fma2(acc[1], xp, va.y);
        }
    }
    float2 a0 = unpack2(acc[0]), a1 = unpack2(acc[1]);
    ((float4*)ed)[n * 2 + 0] = make_float4(__expf(a0.x), __expf(0.2f * a0.x),
                                           __expf(a0.y), __expf(0.2f * a0.y));
    ((float4*)ed)[n * 2 + 1] = make_float4(__expf(a1.x), __expf(0.2f * a1.x),
                                           __expf(a1.y), __expf(0.2f * a1.y));
}

// -------- GATHER conv: warp/dst; no exp, no shuffles ---------------------------
// ee = max(E1s*E1d, E2s*E2d)  ==  exp(lrelu(es+ed))
template <int D>
__global__ void __launch_bounds__(256)
gat_gather(const int* __restrict__ off, const int* __restrict__ srt,
           const float* __restrict__ es, const float* __restrict__ ed,
           const __half* __restrict__ hs, float* __restrict__ acc,
           int Nd, int add, const float* __restrict__ bias0,
           const float* __restrict__ bias1, int relu) {
    constexpr int CPL = D / 32;
    int warp = (blockIdx.x * blockDim.x + threadIdx.x) >> 5;
    int lane = threadIdx.x & 31;
    if (warp >= Nd) return;
    int d = warp;
    int start = __ldg(&off[d]), end = __ldg(&off[d + 1]);
    int h = lane >> 3;
    float2 edv = __ldg((const float2*)(ed + d * 8 + h * 2));
    float E1d = edv.x, E2d = edv.y;
    float den = 0.f;
    float a0 = 0.f, a1 = 0.f, a2 = 0.f, a3 = 0.f;

    int i = start;
    for (; i + 4 <= end; i += 4) {
        int s0 = __ldg(&srt[i + 0]);
        int s1 = __ldg(&srt[i + 1]);
        int s2 = __ldg(&srt[i + 2]);
        int s3 = __ldg(&srt[i + 3]);
        float2 v0 = __ldg((const float2*)(es + s0 * 8 + h * 2));
        float2 v1 = __ldg((const float2*)(es + s1 * 8 + h * 2));
        float2 v2 = __ldg((const float2*)(es + s2 * 8 + h * 2));
        float2 v3 = __ldg((const float2*)(es + s3 * 8 + h * 2));
        float ee0 = fmaxf(v0.x * E1d, v0.y * E2d);
        float ee1 = fmaxf(v1.x * E1d, v1.y * E2d);
        float ee2 = fmaxf(v2.x * E1d, v2.y * E2d);
        float ee3 = fmaxf(v3.x * E1d, v3.y * E2d);
        den += (ee0 + ee1) + (ee2 + ee3);
        if (D == 128) {
            union { uint2 u; __half2 h2[2]; } c0, c1, c2, c3;
            c0.u = *(const uint2*)(hs + (size_t)s0 * D + lane * 4);
            c1.u = *(const uint2*)(hs + (size_t)s1 * D + lane * 4);
            c2.u = *(const uint2*)(hs + (size_t)s2 * D + lane * 4);
            c3.u = *(const uint2*)(hs + (size_t)s3 * D + lane * 4);
            float2 p;
            p = __half22float2(c0.h2[0]); a0 += ee0 * p.x; a1 += ee0 * p.y;
            p = __half22float2(c0.h2[1]); a2 += ee0 * p.x; a3 += ee0 * p.y;
            p = __half22float2(c1.h2[0]); a0 += ee1 * p.x; a1 += ee1 * p.y;
            p = __half22float2(c1.h2[1]); a2 += ee1 * p.x; a3 += ee1 * p.y;
            p = __half22float2(c2.h2[0]); a0 += ee2 * p.x; a1 += ee2 * p.y;
            p = __half22float2(c2.h2[1]); a2 += ee2 * p.x; a3 += ee2 * p.y;
            p = __half22float2(c3.h2[0]); a0 += ee3 * p.x; a1 += ee3 * p.y;
            p = __half22float2(c3.h2[1]); a2 += ee3 * p.x; a3 += ee3 * p.y;
        } else {
            union { unsigned u; __half2 h2; } c0, c1, c2, c3;
            c0.u = *(const unsigned*)(hs + (size_t)s0 * D + lane * 2);
            c1.u = *(const unsigned*)(hs + (size_t)s1 * D + lane * 2);
            c2.u = *(const unsigned*)(hs + (size_t)s2 * D + lane * 2);
            c3.u = *(const unsigned*)(hs + (size_t)s3 * D + lane * 2);
            float2 p;
            p = __half22float2(c0.h2); a0 += ee0 * p.x; a1 += ee0 * p.y;
            p = __half22float2(c1.h2); a0 += ee1 * p.x; a1 += ee1 * p.y;
            p = __half22float2(c2.h2); a0 += ee2 * p.x; a1 += ee2 * p.y;
            p = __half22float2(c3.h2); a0 += ee3 * p.x; a1 += ee3 * p.y;
        }
    }
    for (; i < end; i++) {
        int s = __ldg(&srt[i]);
        float2 v = __ldg((const float2*)(es + s * 8 + h * 2));
        float ee = fmaxf(v.x * E1d, v.y * E2d);
        den += ee;
        if (D == 128) {
            union { uint2 u; __half2 h2[2]; } cv;
            cv.u = *(const uint2*)(hs + (size_t)s * D + lane * 4);
            float2 p0 = __half22float2(cv.h2[0]), p1 = __half22float2(cv.h2[1]);
            a0 += ee * p0.x; a1 += ee * p0.y; a2 += ee * p1.x; a3 += ee * p1.y;
        } else {
            union { unsigned u; __half2 h2; } cv;
            cv.u = *(const unsigned*)(hs + (size_t)s * D + lane * 2);
            float2 p = __half22float2(cv.h2);
            a0 += ee * p.x; a1 += ee * p.y;
        }
    }

    float inv = 1.f / (den + 1e-16f);
    int cb = lane * CPL;
    float* dp = acc + (size_t)d * D + cb;
    if (D == 128) {
        float4 o = make_float4(a0 * inv, a1 * inv, a2 * inv, a3 * inv);
        if (add) {
            float4 pa = *(const float4*)dp;
            o.x += pa.x; o.y += pa.y; o.z += pa.z; o.w += pa.w;
        }
        if (bias0) {
            float4 b = *(const float4*)(bias0 + cb);
            o.x += b.x; o.y += b.y; o.z += b.z; o.w += b.w;
        }
        if (bias1) {
            float4 b = *(const float4*)(bias1 + cb);
            o.x += b.x; o.y += b.y; o.z += b.z; o.w += b.w;
        }
        if (relu) {
            o.x = fmaxf(o.x, 0.f); o.y = fmaxf(o.y, 0.f);
            o.z = fmaxf(o.z, 0.f); o.w = fmaxf(o.w, 0.f);
        }
        *(float4*)dp = o;
    } else {
        float2 o = make_float2(a0 * inv, a1 * inv);
        if (add) {
            float2 pa = *(const float2*)dp;
            o.x += pa.x; o.y += pa.y;
        }
        if (bias0) {
            float2 b = *(const float2*)(bias0 + cb);
            o.x += b.x; o.y += b.y;
        }
        if (bias1) {
            float2 b = *(const float2*)(bias1 + cb);
            o.x += b.x; o.y += b.y;
        }
        if (relu) {
            o.x = fmaxf(o.x, 0.f); o.y = fmaxf(o.y, 0.f);
        }
        *(float2*)dp = o;
    }
}

// =============================================================================
extern "C" void kernel_launch(void* const* d_in, const int* in_sizes, int n_in,
                              void* d_out, int out_size) {
    const float* x_p = (const float*)d_in[0];
    const float* x_a = (const float*)d_in[1];
    const int* src_pp = (const int*)d_in[2];
    const int* dst_pp = (const int*)d_in[3];
    const int* src_ap = (const int*)d_in[4];
    const int* dst_ap = (const int*)d_in[5];
    const int* src_pa = (const int*)d_in[6];
    const int* dst_pa = (const int*)d_in[7];
    const float* Wsrc1 = (const float*)d_in[8];
    const float* Wdst1 = (const float*)d_in[9];
    const float* asrc1 = (const float*)d_in[10];
    const float* adst1 = (const float*)d_in[11];
    const float* b1 = (const float*)d_in[12];
    const float* Wsrc2 = (const float*)d_in[13];
    const float* Wdst2 = (const float*)d_in[14];
    const float* asrc2 = (const float*)d_in[15];
    const float* adst2 = (const float*)d_in[16];
    const float* b2 = (const float*)d_in[17];
    float* out = (float*)d_out;

    void* p;
    cudaGetSymbolAddress(&p, g_hs);     __half* hs  = (__half*)p;
    cudaGetSymbolAddress(&p, g_es);     float* es   = (float*)p;
    cudaGetSymbolAddress(&p, g_ed);     float* ed   = (float*)p;
    cudaGetSymbolAddress(&p, g_accp);   float* accp = (float*)p;
    cudaGetSymbolAddress(&p, g_acca);   float* acca = (float*)p;
    cudaGetSymbolAddress(&p, g_vd1);    float* vd1  = (float*)p;
    cudaGetSymbolAddress(&p, g_vd2);    float* vd2  = (float*)p;
    cudaGetSymbolAddress(&p, g_off_pp); int* off_pp = (int*)p;
    cudaGetSymbolAddress(&p, g_off_ap); int* off_ap = (int*)p;
    cudaGetSymbolAddress(&p, g_off_pa); int* off_pa = (int*)p;
    cudaGetSymbolAddress(&p, g_srt);    int* srt    = (int*)p;
    cudaGetSymbolAddress(&p, g_writer); int* writer = (int*)p;

    int* srt_pp = srt;
    int* srt_ap = srt + EPP;
    int* srt_pa = srt + EPP + EAP;

    float* ed0 = ed;
    float* ed1 = ed + NP * 8;
    float* ed2 = ed + 2 * NP * 8;

    const int TB = 256;
    auto blocks = [](long long n) { return (int)((n + 255) / 256); };

    // ---- batched CSR build (4 launches, reused by both layers) ----
    zero3<<<blocks((NP + 1) + (NP + 1) + (NA + 1)), TB>>>(off_pp, NP + 1, off_ap, NP + 1,
                                                          off_pa, NA + 1);
    count3<<<blocks(EPP + EAP + EPA), TB>>>(dst_pp, dst_ap, dst_pa, off_pp, off_ap, off_pa);
    scan3<<<3, 1024>>>(off_pp, off_ap, off_pa, writer);
    scatter3<<<blocks(EPP + EAP + EPA), TB>>>(src_pp, dst_pp, src_ap, dst_ap,
                                              src_pa, dst_pa, writer, srt);

    compute_vd<<<blocks(2 * 3 * 128 * 4), TB>>>(Wdst1, adst1, Wdst2, adst2, vd1, vd2);

    auto gemm = [&](const float* xs, int Ns, const float* Ws, const float* a_s, int D) {
        dim3 grid(D / 64, (Ns + BM - 1) / BM);
        if (D == 128)
            sgemm_es<32><<<grid, 256>>>(xs, Ws, hs, es, a_s, Ns, D);
        else
            sgemm_es<16><<<grid, 256>>>(xs, Ws, hs, es, a_s, Ns, D);
    };
    auto gather = [&](const int* off, const int* s, float* edr, float* acc,
                      int Nd, int D, int add, const float* bias0,
                      const float* bias1, int relu) {
        int nthreads = Nd * 32;
        if (D == 128)
            gat_gather<128><<<blocks(nthreads), TB>>>(off, s, es, edr, hs, acc,
                                                      Nd, add, bias0, bias1, relu);
        else
            gat_gather<64><<<blocks(nthreads), TB>>>(off, s, es, edr, hs, acc,
                                                     Nd, add, bias0, bias1, relu);
    };

    // ---------------- layer 1 (D=128) ----------------
    ed_nodes2<<<blocks(NP), TB>>>(x_p, vd1 + 0 * 512, vd1 + 1 * 512, ed0, ed1, NP);
    ed_nodes1<<<blocks(NA), TB>>>(x_a, vd1 + 2 * 512, ed2, NA);

    gemm(x_p, NP, Wsrc1 + 0 * 128 * 128, asrc1 + 0 * 128, 128);
    gather(off_pp, srt_pp, ed0, accp, NP, 128, 0, nullptr, nullptr, 0);

    gemm(x_a, NA, Wsrc1 + 1 * 128 * 128, asrc1 + 1 * 128, 128);
    gather(off_ap, srt_ap, ed1, accp, NP, 128, 1, b1 + 0, b1 + 128, 1);

    gemm(x_p, NP, Wsrc1 + 2 * 128 * 128, asrc1 + 2 * 128, 128);
    gather(off_pa, srt_pa, ed2, acca, NA, 128, 0, b1 + 256, nullptr, 1);

    // ---------------- layer 2 (D=64) -> d_out ----------------
    ed_nodes2<<<blocks(NP), TB>>>(accp, vd2 + 0 * 512, vd2 + 1 * 512, ed0, ed1, NP);
    ed_nodes1<<<blocks(NA), TB>>>(acca, vd2 + 2 * 512, ed2, NA);

    gemm(accp, NP, Wsrc2 + 0 * 128 * 64, asrc2 + 0 * 64, 64);
    gather(off_pp, srt_pp, ed0, out, NP, 64, 0, nullptr, nullptr, 0);

    gemm(acca, NA, Wsrc2 + 1 * 128 * 64, asrc2 + 1 * 64, 64);
    gather(off_ap, srt_ap, ed1, out, NP, 64, 1, b2 + 0, b2 + 64, 0);

    gemm(accp, NP, Wsrc2 + 2 * 128 * 64, asrc2 + 2 * 64, 64);
    gather(off_pa, srt_pa, ed2, out + (size_t)NP * 64, NA, 64, 0, b2 + 128, nullptr, 0);
}

// round 11
// speedup vs baseline: 2.6758x; 1.1621x over previous
#include <cuda_runtime.h>
#include <cuda_bf16.h>
#include <cuda_fp16.h>
#include <cstdint>

#define NP 100000
#define NA 50000
#define EPP 1600000
#define EAP 800000
#define EPA 800000

// ---------------- scratch ----------------------------------------------------
__device__ __align__(16) __half g_hs[NP * 128];    // transformed src feats (fp16)
__device__ __align__(16) float g_es[NP * 8];       // per src node/head: (e^x, e^{0.2x})
__device__ __align__(16) float g_ed[3 * NP * 8];   // per relation dst node/head pairs
__device__ __align__(16) float g_accp[NP * 128];
__device__ __align__(16) float g_acca[NA * 128];
__device__ __align__(16) float g_vd1[3 * 128 * 4];
__device__ __align__(16) float g_vd2[3 * 128 * 4];
// CSR scratch
__device__ int g_off_pp[NP + 1];
__device__ int g_off_ap[NP + 1];
__device__ int g_off_pa[NA + 1];
__device__ int g_srt[EPP + EAP + EPA];
__device__ int g_writer[NP + NP + NA];

// ---------------- helpers ----------------------------------------------------
__device__ __forceinline__ unsigned long long pack2(float lo, float hi) {
    unsigned long long r;
    asm("mov.b64 %0, {%1, %2};" : "=l"(r) : "f"(lo), "f"(hi));
    return r;
}
__device__ __forceinline__ void fma2(unsigned long long& d,
                                     unsigned long long a, unsigned long long b) {
    asm("fma.rn.f32x2 %0, %1, %2, %0;" : "+l"(d) : "l"(a), "l"(b));
}
__device__ __forceinline__ float2 unpack2(unsigned long long v) {
    float lo, hi;
    asm("mov.b64 {%0, %1}, %2;" : "=f"(lo), "=f"(hi) : "l"(v));
    return make_float2(lo, hi);
}
__device__ __forceinline__ uint32_t tf32(float x) {
    uint32_t r;
    asm("cvt.rna.tf32.f32 %0, %1;" : "=r"(r) : "f"(x));
    return r;
}
__device__ __forceinline__ void mma_tf32(float* d, const uint32_t* a, const uint32_t* b) {
    asm("mma.sync.aligned.m16n8k8.row.col.f32.tf32.tf32.f32 "
        "{%0,%1,%2,%3},{%4,%5,%6,%7},{%8,%9},{%0,%1,%2,%3};"
        : "+f"(d[0]), "+f"(d[1]), "+f"(d[2]), "+f"(d[3])
        : "r"(a[0]), "r"(a[1]), "r"(a[2]), "r"(a[3]), "r"(b[0]), "r"(b[1]));
}

// ---------------- batched CSR build -------------------------------------------
__global__ void zero3(int* __restrict__ a, int na, int* __restrict__ b, int nb,
                      int* __restrict__ c, int nc) {
    int i = blockIdx.x * blockDim.x + threadIdx.x;
    if (i < na) a[i] = 0;
    else if (i < na + nb) b[i - na] = 0;
    else if (i < na + nb + nc) c[i - na - nb] = 0;
}
__global__ void count3(const int* __restrict__ d0, const int* __restrict__ d1,
                       const int* __restrict__ d2, int* __restrict__ o0,
                       int* __restrict__ o1, int* __restrict__ o2) {
    int i = blockIdx.x * blockDim.x + threadIdx.x;
    if (i < EPP) atomicAdd(&o0[d0[i] + 1], 1);
    else if (i < EPP + EAP) atomicAdd(&o1[d1[i - EPP] + 1], 1);
    else if (i < EPP + EAP + EPA) atomicAdd(&o2[d2[i - EPP - EAP] + 1], 1);
}
__device__ void scan_one(int* __restrict__ off, int* __restrict__ writer, int n, int nw) {
    __shared__ int ssum[1024];
    int tid = threadIdx.x;
    int running = 0;
    for (int base = 0; base < n; base += 4096) {
        int idx = base + tid * 4;
        int v0 = idx + 0 < n ? off[idx + 0] : 0;
        int v1 = idx + 1 < n ? off[idx + 1] : 0;
        int v2 = idx + 2 < n ? off[idx + 2] : 0;
        int v3 = idx + 3 < n ? off[idx + 3] : 0;
        int p0 = v0, p1 = p0 + v1, p2 = p1 + v2, p3 = p2 + v3;
        ssum[tid] = p3;
        __syncthreads();
        for (int o = 1; o < 1024; o <<= 1) {
            int val = 0;
            if (tid >= o) val = ssum[tid - o];
            __syncthreads();
            if (tid >= o) ssum[tid] += val;
            __syncthreads();
        }
        int excl = running + (tid ? ssum[tid - 1] : 0);
        int total = ssum[1023];
        __syncthreads();
        int s0 = excl + p0, s1 = excl + p1, s2 = excl + p2, s3 = excl + p3;
        if (idx + 0 < n) { off[idx + 0] = s0; if (idx + 0 < nw) writer[idx + 0] = s0; }
        if (idx + 1 < n) { off[idx + 1] = s1; if (idx + 1 < nw) writer[idx + 1] = s1; }
        if (idx + 2 < n) { off[idx + 2] = s2; if (idx + 2 < nw) writer[idx + 2] = s2; }
        if (idx + 3 < n) { off[idx + 3] = s3; if (idx + 3 < nw) writer[idx + 3] = s3; }
        running += total;
    }
}
__global__ void __launch_bounds__(1024)
scan3(int* __restrict__ o0, int* __restrict__ o1, int* __restrict__ o2,
      int* __restrict__ writer) {
    if (blockIdx.x == 0)      scan_one(o0, writer, NP + 1, NP);
    else if (blockIdx.x == 1) scan_one(o1, writer + NP, NP + 1, NP);
    else                      scan_one(o2, writer + 2 * NP, NA + 1, NA);
}
__global__ void scatter3(const int* __restrict__ s0, const int* __restrict__ d0,
                         const int* __restrict__ s1, const int* __restrict__ d1,
                         const int* __restrict__ s2, const int* __restrict__ d2,
                         int* __restrict__ writer, int* __restrict__ srt) {
    int i = blockIdx.x * blockDim.x + threadIdx.x;
    if (i < EPP) {
        int pos = atomicAdd(&writer[d0[i]], 1);
        srt[pos] = s0[i];
    } else if (i < EPP + EAP) {
        int e = i - EPP;
        int pos = atomicAdd(&writer[NP + d1[e]], 1);
        srt[EPP + pos] = s1[e];
    } else if (i < EPP + EAP + EPA) {
        int e = i - EPP - EAP;
        int pos = atomicAdd(&writer[2 * NP + d2[e]], 1);
        srt[EPP + EAP + pos] = s2[e];
    }
}

// ---------------- tf32 MMA GEMM + fused exp-pair es epilogue, fp16 C ----------
// C[M,N](fp16) = A[M,128] @ B[128,N]; es pairs from fp32 accumulators.
// 128x64 block, 8 warps at 32x32 warp tiles, m16n8k8 tf32, BK=16 double-buffered.
template <int CC>
__global__ void __launch_bounds__(256)
mma_es(const float* __restrict__ A, const float* __restrict__ B,
       __half* __restrict__ C, float* __restrict__ es,
       const float* __restrict__ a_s, int M, int N) {
    const int K = 128;
    const int BKc = 16;
    __shared__ __align__(16) float As[2][128][BKc + 4];   // row stride 20 -> conflict-free frags
    __shared__ __align__(16) float Bs[2][BKc][64 + 8];    // row stride 72 -> conflict-free frags
    int tid = threadIdx.x;
    int lane = tid & 31, wid = tid >> 5;
    int wm = wid & 3, wn = wid >> 2;          // 4 x 2 warp grid
    int g = lane >> 2, tig = lane & 3;
    int m0 = blockIdx.y * 128, n0 = blockIdx.x * 64;

    float cfr[2][4][4];                        // [mt][nt][c0..c3]
#pragma unroll
    for (int mt = 0; mt < 2; mt++)
#pragma unroll
        for (int nt = 0; nt < 4; nt++)
#pragma unroll
            for (int q = 0; q < 4; q++) cfr[mt][nt][q] = 0.f;

    int aRow = tid >> 1, aK = (tid & 1) * 8;
    int bRow = tid >> 4, bC = (tid & 15) * 4;

    float4 ra0, ra1, rb;
    auto loadg = [&](int k0) {
        int m = m0 + aRow;
        if (m < M) {
            ra0 = *(const float4*)(A + (size_t)m * K + k0 + aK);
            ra1 = *(const float4*)(A + (size_t)m * K + k0 + aK + 4);
        } else {
            ra0 = make_float4(0.f, 0.f, 0.f, 0.f);
            ra1 = ra0;
        }
        rb = *(const float4*)(B + (size_t)(k0 + bRow) * N + n0 + bC);
    };
    auto stores = [&](int buf) {
        *(float4*)&As[buf][aRow][aK] = ra0;
        *(float4*)&As[buf][aRow][aK + 4] = ra1;
        *(float4*)&Bs[buf][bRow][bC] = rb;
    };

    loadg(0);
    stores(0);
    __syncthreads();

#pragma unroll 1
    for (int c = 0; c < 8; c++) {
        if (c + 1 < 8) loadg((c + 1) * BKc);
        int buf = c & 1;
#pragma unroll
        for (int kk = 0; kk < BKc; kk += 8) {
            uint32_t af[2][4], bf[4][2];
#pragma unroll
            for (int mt = 0; mt < 2; mt++) {
                int rm = wm * 32 + mt * 16;
                af[mt][0] = tf32(As[buf][rm + g][kk + tig]);
                af[mt][1] = tf32(As[buf][rm + g + 8][kk + tig]);
                af[mt][2] = tf32(As[buf][rm + g][kk + tig + 4]);
                af[mt][3] = tf32(As[buf][rm + g + 8][kk + tig + 4]);
            }
#pragma unroll
            for (int nt = 0; nt < 4; nt++) {
                int cn = wn * 32 + nt * 8;
                bf[nt][0] = tf32(Bs[buf][kk + tig][cn + g]);
                bf[nt][1] = tf32(Bs[buf][kk + tig + 4][cn + g]);
            }
#pragma unroll
            for (int mt = 0; mt < 2; mt++)
#pragma unroll
                for (int nt = 0; nt < 4; nt++)
                    mma_tf32(cfr[mt][nt], af[mt], bf[nt]);
        }
        if (c + 1 < 8) stores((c + 1) & 1);
        __syncthreads();
    }

    // ---- es epilogue: warp's 32 cols cover 32/CC head(s); shuffle width-4 ----
    {
        constexpr int NH = 32 / CC;            // 1 (layer1) or 2 (layer2)
        float pl[2][NH], ph[2][NH];
#pragma unroll
        for (int mt = 0; mt < 2; mt++)
#pragma unroll
            for (int nh = 0; nh < NH; nh++) { pl[mt][nh] = 0.f; ph[mt][nh] = 0.f; }
#pragma unroll
        for (int nt = 0; nt < 4; nt++) {
            int nh = (nt * 8) / CC;
            float w0 = __ldg(&a_s[n0 + wn * 32 + nt * 8 + 2 * tig]);
            float w1 = __ldg(&a_s[n0 + wn * 32 + nt * 8 + 2 * tig + 1]);
#pragma unroll
            for (int mt = 0; mt < 2; mt++) {
                pl[mt][nh] += cfr[mt][nt][0] * w0 + cfr[mt][nt][1] * w1;
                ph[mt][nh] += cfr[mt][nt][2] * w0 + cfr[mt][nt][3] * w1;
            }
        }
#pragma unroll
        for (int mt = 0; mt < 2; mt++)
#pragma unroll
            for (int nh = 0; nh < NH; nh++) {
#pragma unroll
                for (int off = 1; off < 4; off <<= 1) {
                    pl[mt][nh] += __shfl_xor_sync(0xffffffffu, pl[mt][nh], off, 4);
                    ph[mt][nh] += __shfl_xor_sync(0xffffffffu, ph[mt][nh], off, 4);
                }
                if (tig == 0) {
                    int h = (n0 + wn * 32) / CC + nh;
                    int m_lo = m0 + wm * 32 + mt * 16 + g;
                    int m_hi = m_lo + 8;
                    if (m_lo < M)
                        *(float2*)(es + m_lo * 8 + h * 2) =
                            make_float2(__expf(pl[mt][nh]), __expf(0.2f * pl[mt][nh]));
                    if (m_hi < M)
                        *(float2*)(es + m_hi * 8 + h * 2) =
                            make_float2(__expf(ph[mt][nh]), __expf(0.2f * ph[mt][nh]));
                }
            }
    }

    // ---- fp16 C store from fragments ----
#pragma unroll
    for (int mt = 0; mt < 2; mt++) {
        int m_lo = m0 + wm * 32 + mt * 16 + g;
        int m_hi = m_lo + 8;
#pragma unroll
        for (int nt = 0; nt < 4; nt++) {
            int col = n0 + wn * 32 + nt * 8 + 2 * tig;
            if (m_lo < M)
                *(__half2*)(C + (size_t)m_lo * N + col) =
                    __floats2half2_rn(cfr[mt][nt][0], cfr[mt][nt][1]);
            if (m_hi < M)
                *(__half2*)(C + (size_t)m_hi * N + col) =
                    __floats2half2_rn(cfr[mt][nt][2], cfr[mt][nt][3]);
        }
    }
}

// ---------------- vd folding ---------------------------------------------------
__global__ void compute_vd(const float* __restrict__ Wd1, const float* __restrict__ ad1,
                           const float* __restrict__ Wd2, const float* __restrict__ ad2,
                           float* __restrict__ vd1, float* __restrict__ vd2) {
    int i = blockIdx.x * blockDim.x + threadIdx.x;
    if (i >= 2 * 3 * 128 * 4) return;
    int layer = i >= 3 * 128 * 4;
    int ii = i - layer * 3 * 128 * 4;
    int h = ii & 3;
    int f = (ii >> 2) & 127;
    int r = ii >> 9;
    int D = layer ? 64 : 128;
    int C = D / 4;
    const float* W = (layer ? Wd2 : Wd1) + (size_t)r * 128 * D + (size_t)f * D + h * C;
    const float* a = (layer ? ad2 : ad1) + r * 4 * C + h * C;
    float s = 0.f;
    for (int c = 0; c < C; c++) s += W[c] * a[c];
    (layer ? vd2 : vd1)[r * 512 + f * 4 + h] = s;
}

// -------- ed, thread-per-node, TWO relations; writes exp pairs -----------------
__global__ void __launch_bounds__(256)
ed_nodes2(const float* __restrict__ x,
          const float* __restrict__ vdA, const float* __restrict__ vdB,
          float* __restrict__ edA, float* __restrict__ edB, int N) {
    __shared__ __align__(16) float sv[1024];
    int t = threadIdx.x;
    ((float4*)sv)[t] = (t < 128) ? ((const float4*)vdA)[t]
                                 : ((const float4*)vdB)[t - 128];
    __syncthreads();
    int n = blockIdx.x * blockDim.x + t;
    if (n >= N) return;
    unsigned long long accA[2] = {0ull, 0ull}, accB[2] = {0ull, 0ull};
    const float4* xr = (const float4*)(x + (size_t)n * 128);
#pragma unroll 8
    for (int r = 0; r < 32; r++) {
        float4 xv = xr[r];
#pragma unroll
        for (int j = 0; j < 4; j++) {
            float xs = j == 0 ? xv.x : j == 1 ? xv.y : j == 2 ? xv.z : xv.w;
            unsigned long long xp = pack2(xs, xs);
            ulonglong2 va = *(const ulonglong2*)&sv[(4 * r + j) * 4];
            fma2(accA[0], xp, va.x);
            fma2(accA[1], xp, va.y);
            ulonglong2 vb = *(const ulonglong2*)&sv[512 + (4 * r + j) * 4];
            fma2(accB[0], xp, vb.x);
            fma2(accB[1], xp, vb.y);
        }
    }
    float2 a0 = unpack2(accA[0]), a1 = unpack2(accA[1]);
    float2 b0 = unpack2(accB[0]), b1 = unpack2(accB[1]);
    ((float4*)edA)[n * 2 + 0] = make_float4(__expf(a0.x), __expf(0.2f * a0.x),
                                            __expf(a0.y), __expf(0.2f * a0.y));
    ((float4*)edA)[n * 2 + 1] = make_float4(__expf(a1.x), __expf(0.2f * a1.x),
                                            __expf(a1.y), __expf(0.2f * a1.y));
    ((float4*)edB)[n * 2 + 0] = make_float4(__expf(b0.x), __expf(0.2f * b0.x),
                                            __expf(b0.y), __expf(0.2f * b0.y));
    ((float4*)edB)[n * 2 + 1] = make_float4(__expf(b1.x), __expf(0.2f * b1.x),
                                            __expf(b1.y), __expf(0.2f * b1.y));
}

__global__ void __launch_bounds__(256)
ed_nodes1(const float* __restrict__ x, const float* __restrict__ vd,
          float* __restrict__ ed, int N) {
    __shared__ __align__(16) float sv[512];
    int t = threadIdx.x;
    if (t < 128) ((float4*)sv)[t] = ((const float4*)vd)[t];
    __syncthreads();
    int n = blockIdx.x * blockDim.x + t;
    if (n >= N) return;
    unsigned long long acc[2] = {0ull, 0ull};
    const float4* xr = (const float4*)(x + (size_t)n * 128);
#pragma unroll 8
    for (int r = 0; r < 32; r++) {
        float4 xv = xr[r];
#pragma unroll
        for (int j = 0; j < 4; j++) {
            float xs = j == 0 ? xv.x : j == 1 ? xv.y : j == 2 ? xv.z : xv.w;
            unsigned long long xp = pack2(xs, xs);
            ulonglong2 va = *(const ulonglong2*)&sv[(4 * r + j) * 4];
            fma2(acc[0], xp, va.x);
            fma2(acc[1], xp, va.y);
        }
    }
    float2 a0 = unpack2(acc[0]), a1 = unpack2(acc[1]);
    ((float4*)ed)[n * 2 + 0] = make_float4(__expf(a0.x), __expf(0.2f * a0.x),
                                           __expf(a0.y), __expf(0.2f * a0.y));
    ((float4*)ed)[n * 2 + 1] = make_float4(__expf(a1.x), __expf(0.2f * a1.x),
                                           __expf(a1.y), __expf(0.2f * a1.y));
}

// -------- GATHER conv: warp/dst; no exp, no shuffles ---------------------------
template <int D>
__global__ void __launch_bounds__(256)
gat_gather(const int* __restrict__ off, const int* __restrict__ srt,
           const float* __restrict__ es, const float* __restrict__ ed,
           const __half* __restrict__ hs, float* __restrict__ acc,
           int Nd, int add, const float* __restrict__ bias0,
           const float* __restrict__ bias1, int relu) {
    constexpr int CPL = D / 32;
    int warp = (blockIdx.x * blockDim.x + threadIdx.x) >> 5;
    int lane = threadIdx.x & 31;
    if (warp >= Nd) return;
    int d = warp;
    int start = __ldg(&off[d]), end = __ldg(&off[d + 1]);
    int h = lane >> 3;
    float2 edv = __ldg((const float2*)(ed + d * 8 + h * 2));
    float E1d = edv.x, E2d = edv.y;
    float den = 0.f;
    float a0 = 0.f, a1 = 0.f, a2 = 0.f, a3 = 0.f;

    int i = start;
    for (; i + 4 <= end; i += 4) {
        int s0 = __ldg(&srt[i + 0]);
        int s1 = __ldg(&srt[i + 1]);
        int s2 = __ldg(&srt[i + 2]);
        int s3 = __ldg(&srt[i + 3]);
        float2 v0 = __ldg((const float2*)(es + s0 * 8 + h * 2));
        float2 v1 = __ldg((const float2*)(es + s1 * 8 + h * 2));
        float2 v2 = __ldg((const float2*)(es + s2 * 8 + h * 2));
        float2 v3 = __ldg((const float2*)(es + s3 * 8 + h * 2));
        float ee0 = fmaxf(v0.x * E1d, v0.y * E2d);
        float ee1 = fmaxf(v1.x * E1d, v1.y * E2d);
        float ee2 = fmaxf(v2.x * E1d, v2.y * E2d);
        float ee3 = fmaxf(v3.x * E1d, v3.y * E2d);
        den += (ee0 + ee1) + (ee2 + ee3);
        if (D == 128) {
            union { uint2 u; __half2 h2[2]; } c0, c1, c2, c3;
            c0.u = *(const uint2*)(hs + (size_t)s0 * D + lane * 4);
            c1.u = *(const uint2*)(hs + (size_t)s1 * D + lane * 4);
            c2.u = *(const uint2*)(hs + (size_t)s2 * D + lane * 4);
            c3.u = *(const uint2*)(hs + (size_t)s3 * D + lane * 4);
            float2 p;
            p = __half22float2(c0.h2[0]); a0 += ee0 * p.x; a1 += ee0 * p.y;
            p = __half22float2(c0.h2[1]); a2 += ee0 * p.x; a3 += ee0 * p.y;
            p = __half22float2(c1.h2[0]); a0 += ee1 * p.x; a1 += ee1 * p.y;
            p = __half22float2(c1.h2[1]); a2 += ee1 * p.x; a3 += ee1 * p.y;
            p = __half22float2(c2.h2[0]); a0 += ee2 * p.x; a1 += ee2 * p.y;
            p = __half22float2(c2.h2[1]); a2 += ee2 * p.x; a3 += ee2 * p.y;
            p = __half22float2(c3.h2[0]); a0 += ee3 * p.x; a1 += ee3 * p.y;
            p = __half22float2(c3.h2[1]); a2 += ee3 * p.x; a3 += ee3 * p.y;
        } else {
            union { unsigned u; __half2 h2; } c0, c1, c2, c3;
            c0.u = *(const unsigned*)(hs + (size_t)s0 * D + lane * 2);
            c1.u = *(const unsigned*)(hs + (size_t)s1 * D + lane * 2);
            c2.u = *(const unsigned*)(hs + (size_t)s2 * D + lane * 2);
            c3.u = *(const unsigned*)(hs + (size_t)s3 * D + lane * 2);
            float2 p;
            p = __half22float2(c0.h2); a0 += ee0 * p.x; a1 += ee0 * p.y;
            p = __half22float2(c1.h2); a0 += ee1 * p.x; a1 += ee1 * p.y;
            p = __half22float2(c2.h2); a0 += ee2 * p.x; a1 += ee2 * p.y;
            p = __half22float2(c3.h2); a0 += ee3 * p.x; a1 += ee3 * p.y;
        }
    }
    for (; i < end; i++) {
        int s = __ldg(&srt[i]);
        float2 v = __ldg((const float2*)(es + s * 8 + h * 2));
        float ee = fmaxf(v.x * E1d, v.y * E2d);
        den += ee;
        if (D == 128) {
            union { uint2 u; __half2 h2[2]; } cv;
            cv.u = *(const uint2*)(hs + (size_t)s * D + lane * 4);
            float2 p0 = __half22float2(cv.h2[0]), p1 = __half22float2(cv.h2[1]);
            a0 += ee * p0.x; a1 += ee * p0.y; a2 += ee * p1.x; a3 += ee * p1.y;
        } else {
            union { unsigned u; __half2 h2; } cv;
            cv.u = *(const unsigned*)(hs + (size_t)s * D + lane * 2);
            float2 p = __half22float2(cv.h2);
            a0 += ee * p.x; a1 += ee * p.y;
        }
    }

    float inv = 1.f / (den + 1e-16f);
    int cb = lane * CPL;
    float* dp = acc + (size_t)d * D + cb;
    if (D == 128) {
        float4 o = make_float4(a0 * inv, a1 * inv, a2 * inv, a3 * inv);
        if (add) {
            float4 pa = *(const float4*)dp;
            o.x += pa.x; o.y += pa.y; o.z += pa.z; o.w += pa.w;
        }
        if (bias0) {
            float4 b = *(const float4*)(bias0 + cb);
            o.x += b.x; o.y += b.y; o.z += b.z; o.w += b.w;
        }
        if (bias1) {
            float4 b = *(const float4*)(bias1 + cb);
            o.x += b.x; o.y += b.y; o.z += b.z; o.w += b.w;
        }
        if (relu) {
            o.x = fmaxf(o.x, 0.f); o.y = fmaxf(o.y, 0.f);
            o.z = fmaxf(o.z, 0.f); o.w = fmaxf(o.w, 0.f);
        }
        *(float4*)dp = o;
    } else {
        float2 o = make_float2(a0 * inv, a1 * inv);
        if (add) {
            float2 pa = *(const float2*)dp;
            o.x += pa.x; o.y += pa.y;
        }
        if (bias0) {
            float2 b = *(const float2*)(bias0 + cb);
            o.x += b.x; o.y += b.y;
        }
        if (bias1) {
            float2 b = *(const float2*)(bias1 + cb);
            o.x += b.x; o.y += b.y;
        }
        if (relu) {
            o.x = fmaxf(o.x, 0.f); o.y = fmaxf(o.y, 0.f);
        }
        *(float2*)dp = o;
    }
}

// =============================================================================
extern "C" void kernel_launch(void* const* d_in, const int* in_sizes, int n_in,
                              void* d_out, int out_size) {
    const float* x_p = (const float*)d_in[0];
    const float* x_a = (const float*)d_in[1];
    const int* src_pp = (const int*)d_in[2];
    const int* dst_pp = (const int*)d_in[3];
    const int* src_ap = (const int*)d_in[4];
    const int* dst_ap = (const int*)d_in[5];
    const int* src_pa = (const int*)d_in[6];
    const int* dst_pa = (const int*)d_in[7];
    const float* Wsrc1 = (const float*)d_in[8];
    const float* Wdst1 = (const float*)d_in[9];
    const float* asrc1 = (const float*)d_in[10];
    const float* adst1 = (const float*)d_in[11];
    const float* b1 = (const float*)d_in[12];
    const float* Wsrc2 = (const float*)d_in[13];
    const float* Wdst2 = (const float*)d_in[14];
    const float* asrc2 = (const float*)d_in[15];
    const float* adst2 = (const float*)d_in[16];
    const float* b2 = (const float*)d_in[17];
    float* out = (float*)d_out;

    void* p;
    cudaGetSymbolAddress(&p, g_hs);     __half* hs  = (__half*)p;
    cudaGetSymbolAddress(&p, g_es);     float* es   = (float*)p;
    cudaGetSymbolAddress(&p, g_ed);     float* ed   = (float*)p;
    cudaGetSymbolAddress(&p, g_accp);   float* accp = (float*)p;
    cudaGetSymbolAddress(&p, g_acca);   float* acca = (float*)p;
    cudaGetSymbolAddress(&p, g_vd1);    float* vd1  = (float*)p;
    cudaGetSymbolAddress(&p, g_vd2);    float* vd2  = (float*)p;
    cudaGetSymbolAddress(&p, g_off_pp); int* off_pp = (int*)p;
    cudaGetSymbolAddress(&p, g_off_ap); int* off_ap = (int*)p;
    cudaGetSymbolAddress(&p, g_off_pa); int* off_pa = (int*)p;
    cudaGetSymbolAddress(&p, g_srt);    int* srt    = (int*)p;
    cudaGetSymbolAddress(&p, g_writer); int* writer = (int*)p;

    int* srt_pp = srt;
    int* srt_ap = srt + EPP;
    int* srt_pa = srt + EPP + EAP;

    float* ed0 = ed;
    float* ed1 = ed + NP * 8;
    float* ed2 = ed + 2 * NP * 8;

    const int TB = 256;
    auto blocks = [](long long n) { return (int)((n + 255) / 256); };

    // ---- batched CSR build ----
    zero3<<<blocks((NP + 1) + (NP + 1) + (NA + 1)), TB>>>(off_pp, NP + 1, off_ap, NP + 1,
                                                          off_pa, NA + 1);
    count3<<<blocks(EPP + EAP + EPA), TB>>>(dst_pp, dst_ap, dst_pa, off_pp, off_ap, off_pa);
    scan3<<<3, 1024>>>(off_pp, off_ap, off_pa, writer);
    scatter3<<<blocks(EPP + EAP + EPA), TB>>>(src_pp, dst_pp, src_ap, dst_ap,
                                              src_pa, dst_pa, writer, srt);

    compute_vd<<<blocks(2 * 3 * 128 * 4), TB>>>(Wdst1, adst1, Wdst2, adst2, vd1, vd2);

    auto gemm = [&](const float* xs, int Ns, const float* Ws, const float* a_s, int D) {
        dim3 grid(D / 64, (Ns + 127) / 128);
        if (D == 128)
            mma_es<32><<<grid, 256>>>(xs, Ws, hs, es, a_s, Ns, D);
        else
            mma_es<16><<<grid, 256>>>(xs, Ws, hs, es, a_s, Ns, D);
    };
    auto gather = [&](const int* off, const int* s, float* edr, float* acc,
                      int Nd, int D, int add, const float* bias0,
                      const float* bias1, int relu) {
        int nthreads = Nd * 32;
        if (D == 128)
            gat_gather<128><<<blocks(nthreads), TB>>>(off, s, es, edr, hs, acc,
                                                      Nd, add, bias0, bias1, relu);
        else
            gat_gather<64><<<blocks(nthreads), TB>>>(off, s, es, edr, hs, acc,
                                                     Nd, add, bias0, bias1, relu);
    };

    // ---------------- layer 1 (D=128) ----------------
    ed_nodes2<<<blocks(NP), TB>>>(x_p, vd1 + 0 * 512, vd1 + 1 * 512, ed0, ed1, NP);
    ed_nodes1<<<blocks(NA), TB>>>(x_a, vd1 + 2 * 512, ed2, NA);

    gemm(x_p, NP, Wsrc1 + 0 * 128 * 128, asrc1 + 0 * 128, 128);
    gather(off_pp, srt_pp, ed0, accp, NP, 128, 0, nullptr, nullptr, 0);

    gemm(x_a, NA, Wsrc1 + 1 * 128 * 128, asrc1 + 1 * 128, 128);
    gather(off_ap, srt_ap, ed1, accp, NP, 128, 1, b1 + 0, b1 + 128, 1);

    gemm(x_p, NP, Wsrc1 + 2 * 128 * 128, asrc1 + 2 * 128, 128);
    gather(off_pa, srt_pa, ed2, acca, NA, 128, 0, b1 + 256, nullptr, 1);

    // ---------------- layer 2 (D=64) -> d_out ----------------
    ed_nodes2<<<blocks(NP), TB>>>(accp, vd2 + 0 * 512, vd2 + 1 * 512, ed0, ed1, NP);
    ed_nodes1<<<blocks(NA), TB>>>(acca, vd2 + 2 * 512, ed2, NA);

    gemm(accp, NP, Wsrc2 + 0 * 128 * 64, asrc2 + 0 * 64, 64);
    gather(off_pp, srt_pp, ed0, out, NP, 64, 0, nullptr, nullptr, 0);

    gemm(acca, NA, Wsrc2 + 1 * 128 * 64, asrc2 + 1 * 64, 64);
    gather(off_ap, srt_ap, ed1, out, NP, 64, 1, b2 + 0, b2 + 64, 0);

    gemm(accp, NP, Wsrc2 + 2 * 128 * 64, asrc2 + 2 * 64, 64);
    gather(off_pa, srt_pa, ed2, out + (size_t)NP * 64, NA, 64, 0, b2 + 128, nullptr, 0);
}

// round 12
// speedup vs baseline: 2.8953x; 1.0820x over previous
#include <cuda_runtime.h>
#include <cuda_bf16.h>
#include <cuda_fp16.h>
#include <cstdint>

#define NP 100000
#define NA 50000
#define EPP 1600000
#define EAP 800000
#define EPA 800000

// ---------------- scratch ----------------------------------------------------
__device__ __align__(16) __half g_hs0[NP * 128];   // per-relation transformed feats
__device__ __align__(16) __half g_hs1[NA * 128];
__device__ __align__(16) __half g_hs2[NP * 128];
__device__ __align__(16) float g_es[3 * NP * 8];   // (e^x, e^{0.2x}) pairs per node/head
__device__ __align__(16) float g_ed[3 * NP * 8];
__device__ __align__(16) float g_accp[NP * 128];
__device__ __align__(16) float g_acca[NA * 128];
__device__ __align__(16) float g_vd1[3 * 512];
__device__ __align__(16) float g_vd2[3 * 512];
// CSR scratch
__device__ int g_off_pp[NP + 1];
__device__ int g_off_ap[NP + 1];
__device__ int g_off_pa[NA + 1];
__device__ int g_srt[EPP + EAP + EPA];
__device__ int g_writer[NP + NP + NA];

// ---------------- helpers ----------------------------------------------------
__device__ __forceinline__ uint32_t tf32(float x) {
    uint32_t r;
    asm("cvt.rna.tf32.f32 %0, %1;" : "=r"(r) : "f"(x));
    return r;
}
__device__ __forceinline__ void mma_tf32(float* d, const uint32_t* a, const uint32_t* b) {
    asm("mma.sync.aligned.m16n8k8.row.col.f32.tf32.tf32.f32 "
        "{%0,%1,%2,%3},{%4,%5,%6,%7},{%8,%9},{%0,%1,%2,%3};"
        : "+f"(d[0]), "+f"(d[1]), "+f"(d[2]), "+f"(d[3])
        : "r"(a[0]), "r"(a[1]), "r"(a[2]), "r"(a[3]), "r"(b[0]), "r"(b[1]));
}

// ---------------- batched CSR build -------------------------------------------
__global__ void zero3(int* __restrict__ a, int na, int* __restrict__ b, int nb,
                      int* __restrict__ c, int nc) {
    int i = blockIdx.x * blockDim.x + threadIdx.x;
    if (i < na) a[i] = 0;
    else if (i < na + nb) b[i - na] = 0;
    else if (i < na + nb + nc) c[i - na - nb] = 0;
}
__global__ void count3(const int* __restrict__ d0, const int* __restrict__ d1,
                       const int* __restrict__ d2, int* __restrict__ o0,
                       int* __restrict__ o1, int* __restrict__ o2) {
    int i = blockIdx.x * blockDim.x + threadIdx.x;
    if (i < EPP) atomicAdd(&o0[d0[i] + 1], 1);
    else if (i < EPP + EAP) atomicAdd(&o1[d1[i - EPP] + 1], 1);
    else if (i < EPP + EAP + EPA) atomicAdd(&o2[d2[i - EPP - EAP] + 1], 1);
}
__device__ void scan_one(int* __restrict__ off, int* __restrict__ writer, int n, int nw) {
    __shared__ int ssum[1024];
    int tid = threadIdx.x;
    int running = 0;
    for (int base = 0; base < n; base += 4096) {
        int idx = base + tid * 4;
        int v0 = idx + 0 < n ? off[idx + 0] : 0;
        int v1 = idx + 1 < n ? off[idx + 1] : 0;
        int v2 = idx + 2 < n ? off[idx + 2] : 0;
        int v3 = idx + 3 < n ? off[idx + 3] : 0;
        int p0 = v0, p1 = p0 + v1, p2 = p1 + v2, p3 = p2 + v3;
        ssum[tid] = p3;
        __syncthreads();
        for (int o = 1; o < 1024; o <<= 1) {
            int val = 0;
            if (tid >= o) val = ssum[tid - o];
            __syncthreads();
            if (tid >= o) ssum[tid] += val;
            __syncthreads();
        }
        int excl = running + (tid ? ssum[tid - 1] : 0);
        int total = ssum[1023];
        __syncthreads();
        int s0 = excl + p0, s1 = excl + p1, s2 = excl + p2, s3 = excl + p3;
        if (idx + 0 < n) { off[idx + 0] = s0; if (idx + 0 < nw) writer[idx + 0] = s0; }
        if (idx + 1 < n) { off[idx + 1] = s1; if (idx + 1 < nw) writer[idx + 1] = s1; }
        if (idx + 2 < n) { off[idx + 2] = s2; if (idx + 2 < nw) writer[idx + 2] = s2; }
        if (idx + 3 < n) { off[idx + 3] = s3; if (idx + 3 < nw) writer[idx + 3] = s3; }
        running += total;
    }
}
__global__ void __launch_bounds__(1024)
scan3(int* __restrict__ o0, int* __restrict__ o1, int* __restrict__ o2,
      int* __restrict__ writer) {
    if (blockIdx.x == 0)      scan_one(o0, writer, NP + 1, NP);
    else if (blockIdx.x == 1) scan_one(o1, writer + NP, NP + 1, NP);
    else                      scan_one(o2, writer + 2 * NP, NA + 1, NA);
}
__global__ void scatter3(const int* __restrict__ s0, const int* __restrict__ d0,
                         const int* __restrict__ s1, const int* __restrict__ d1,
                         const int* __restrict__ s2, const int* __restrict__ d2,
                         int* __restrict__ writer, int* __restrict__ srt) {
    int i = blockIdx.x * blockDim.x + threadIdx.x;
    if (i < EPP) {
        int pos = atomicAdd(&writer[d0[i]], 1);
        srt[pos] = s0[i];
    } else if (i < EPP + EAP) {
        int e = i - EPP;
        int pos = atomicAdd(&writer[NP + d1[e]], 1);
        srt[EPP + pos] = s1[e];
    } else if (i < EPP + EAP + EPA) {
        int e = i - EPP - EAP;
        int pos = atomicAdd(&writer[2 * NP + d2[e]], 1);
        srt[EPP + EAP + pos] = s2[e];
    }
}

// ---------------- vd folding ---------------------------------------------------
__global__ void compute_vd(const float* __restrict__ Wd1, const float* __restrict__ ad1,
                           const float* __restrict__ Wd2, const float* __restrict__ ad2,
                           float* __restrict__ vd1, float* __restrict__ vd2) {
    int i = blockIdx.x * blockDim.x + threadIdx.x;
    if (i >= 2 * 3 * 128 * 4) return;
    int layer = i >= 3 * 128 * 4;
    int ii = i - layer * 3 * 128 * 4;
    int h = ii & 3;
    int f = (ii >> 2) & 127;
    int r = ii >> 9;
    int D = layer ? 64 : 128;
    int C = D / 4;
    const float* W = (layer ? Wd2 : Wd1) + (size_t)r * 128 * D + (size_t)f * D + h * C;
    const float* a = (layer ? ad2 : ad1) + r * 4 * C + h * C;
    float s = 0.f;
    for (int c = 0; c < C; c++) s += W[c] * a[c];
    (layer ? vd2 : vd1)[r * 512 + f * 4 + h] = s;
}

// ---------------- tf32 MMA GEMM + es epilogue + fused ed (up to 2 relations) ---
// C[M,N](fp16) = A[M,128] @ B[128,N];  es pairs;  ed = A @ vd (8 cols) for NED rel.
template <int CC, int NED>
__global__ void __launch_bounds__(256)
mma_es(const float* __restrict__ A, const float* __restrict__ B,
       __half* __restrict__ C, float* __restrict__ es,
       const float* __restrict__ a_s,
       const float* __restrict__ vdA, const float* __restrict__ vdB,
       float* __restrict__ edA, float* __restrict__ edB,
       int M, int N) {
    const int K = 128;
    const int BKc = 16;
    __shared__ __align__(16) float As[2][128][BKc + 4];
    __shared__ __align__(16) float Bs[2][BKc][64 + 8];
    __shared__ __align__(16) float vds[128][8];
    int tid = threadIdx.x;
    int lane = tid & 31, wid = tid >> 5;
    int wm = wid & 3, wn = wid >> 2;
    int g = lane >> 2, tig = lane & 3;
    int m0 = blockIdx.y * 128, n0 = blockIdx.x * 64;

    if (NED > 0) {
        for (int i = tid; i < 1024; i += 256) {
            int k = i >> 3, j = i & 7;
            float v = 0.f;
            if (j < 4) v = vdA[k * 4 + j];
            else if (NED == 2) v = vdB[k * 4 + (j - 4)];
            vds[k][j] = v;
        }
    }

    float cfr[2][4][4];
#pragma unroll
    for (int mt = 0; mt < 2; mt++)
#pragma unroll
        for (int nt = 0; nt < 4; nt++)
#pragma unroll
            for (int q = 0; q < 4; q++) cfr[mt][nt][q] = 0.f;
    float edf[2][4];
#pragma unroll
    for (int mt = 0; mt < 2; mt++)
#pragma unroll
        for (int q = 0; q < 4; q++) edf[mt][q] = 0.f;
    bool do_ed = (NED > 0) && (wn == 0) && (blockIdx.x == 0);

    int aRow = tid >> 1, aK = (tid & 1) * 8;
    int bRow = tid >> 4, bC = (tid & 15) * 4;

    float4 ra0, ra1, rb;
    auto loadg = [&](int k0) {
        int m = m0 + aRow;
        if (m < M) {
            ra0 = *(const float4*)(A + (size_t)m * K + k0 + aK);
            ra1 = *(const float4*)(A + (size_t)m * K + k0 + aK + 4);
        } else {
            ra0 = make_float4(0.f, 0.f, 0.f, 0.f);
            ra1 = ra0;
        }
        rb = *(const float4*)(B + (size_t)(k0 + bRow) * N + n0 + bC);
    };
    auto stores = [&](int buf) {
        *(float4*)&As[buf][aRow][aK] = ra0;
        *(float4*)&As[buf][aRow][aK + 4] = ra1;
        *(float4*)&Bs[buf][bRow][bC] = rb;
    };

    loadg(0);
    stores(0);
    __syncthreads();

#pragma unroll 1
    for (int c = 0; c < 8; c++) {
        if (c + 1 < 8) loadg((c + 1) * BKc);
        int buf = c & 1;
#pragma unroll
        for (int kk = 0; kk < BKc; kk += 8) {
            uint32_t af[2][4], bf[4][2];
#pragma unroll
            for (int mt = 0; mt < 2; mt++) {
                int rm = wm * 32 + mt * 16;
                af[mt][0] = tf32(As[buf][rm + g][kk + tig]);
                af[mt][1] = tf32(As[buf][rm + g + 8][kk + tig]);
                af[mt][2] = tf32(As[buf][rm + g][kk + tig + 4]);
                af[mt][3] = tf32(As[buf][rm + g + 8][kk + tig + 4]);
            }
#pragma unroll
            for (int nt = 0; nt < 4; nt++) {
                int cn = wn * 32 + nt * 8;
                bf[nt][0] = tf32(Bs[buf][kk + tig][cn + g]);
                bf[nt][1] = tf32(Bs[buf][kk + tig + 4][cn + g]);
            }
#pragma unroll
            for (int mt = 0; mt < 2; mt++)
#pragma unroll
                for (int nt = 0; nt < 4; nt++)
                    mma_tf32(cfr[mt][nt], af[mt], bf[nt]);
            if (do_ed) {
                uint32_t bvd[2];
                int kg = c * BKc + kk;
                bvd[0] = tf32(vds[kg + tig][g]);
                bvd[1] = tf32(vds[kg + tig + 4][g]);
                mma_tf32(edf[0], af[0], bvd);
                mma_tf32(edf[1], af[1], bvd);
            }
        }
        if (c + 1 < 8) stores((c + 1) & 1);
        __syncthreads();
    }

    // ---- ed epilogue: fragment (m, col) -> (rel, head) exp-pairs ----
    if (do_ed) {
        auto edst = [&](int m, int col, float v) {
            int rel = col >> 2;
            if (rel == 1 && NED < 2) return;
            int h = col & 3;
            float* dst = rel ? edB : edA;
            if (m < M)
                *(float2*)(dst + m * 8 + h * 2) =
                    make_float2(__expf(v), __expf(0.2f * v));
        };
#pragma unroll
        for (int mt = 0; mt < 2; mt++) {
            int m_lo = m0 + wm * 32 + mt * 16 + g;
            int m_hi = m_lo + 8;
            edst(m_lo, 2 * tig + 0, edf[mt][0]);
            edst(m_lo, 2 * tig + 1, edf[mt][1]);
            edst(m_hi, 2 * tig + 0, edf[mt][2]);
            edst(m_hi, 2 * tig + 1, edf[mt][3]);
        }
    }

    // ---- es epilogue ----
    {
        constexpr int NH = 32 / CC;
        float pl[2][NH], ph[2][NH];
#pragma unroll
        for (int mt = 0; mt < 2; mt++)
#pragma unroll
            for (int nh = 0; nh < NH; nh++) { pl[mt][nh] = 0.f; ph[mt][nh] = 0.f; }
#pragma unroll
        for (int nt = 0; nt < 4; nt++) {
            int nh = (nt * 8) / CC;
            float w0 = __ldg(&a_s[n0 + wn * 32 + nt * 8 + 2 * tig]);
            float w1 = __ldg(&a_s[n0 + wn * 32 + nt * 8 + 2 * tig + 1]);
#pragma unroll
            for (int mt = 0; mt < 2; mt++) {
                pl[mt][nh] += cfr[mt][nt][0] * w0 + cfr[mt][nt][1] * w1;
                ph[mt][nh] += cfr[mt][nt][2] * w0 + cfr[mt][nt][3] * w1;
            }
        }
#pragma unroll
        for (int mt = 0; mt < 2; mt++)
#pragma unroll
            for (int nh = 0; nh < NH; nh++) {
#pragma unroll
                for (int off = 1; off < 4; off <<= 1) {
                    pl[mt][nh] += __shfl_xor_sync(0xffffffffu, pl[mt][nh], off, 4);
                    ph[mt][nh] += __shfl_xor_sync(0xffffffffu, ph[mt][nh], off, 4);
                }
                if (tig == 0) {
                    int h = (n0 + wn * 32) / CC + nh;
                    int m_lo = m0 + wm * 32 + mt * 16 + g;
                    int m_hi = m_lo + 8;
                    if (m_lo < M)
                        *(float2*)(es + m_lo * 8 + h * 2) =
                            make_float2(__expf(pl[mt][nh]), __expf(0.2f * pl[mt][nh]));
                    if (m_hi < M)
                        *(float2*)(es + m_hi * 8 + h * 2) =
                            make_float2(__expf(ph[mt][nh]), __expf(0.2f * ph[mt][nh]));
                }
            }
    }

    // ---- fp16 C store ----
#pragma unroll
    for (int mt = 0; mt < 2; mt++) {
        int m_lo = m0 + wm * 32 + mt * 16 + g;
        int m_hi = m_lo + 8;
#pragma unroll
        for (int nt = 0; nt < 4; nt++) {
            int col = n0 + wn * 32 + nt * 8 + 2 * tig;
            if (m_lo < M)
                *(__half2*)(C + (size_t)m_lo * N + col) =
                    __floats2half2_rn(cfr[mt][nt][0], cfr[mt][nt][1]);
            if (m_hi < M)
                *(__half2*)(C + (size_t)m_hi * N + col) =
                    __floats2half2_rn(cfr[mt][nt][2], cfr[mt][nt][3]);
        }
    }
}

// -------- shared per-relation edge accumulation (no exp, no shuffles) ----------
template <int D>
__device__ __forceinline__ void edge_accum(
        const int* __restrict__ off, const int* __restrict__ srt,
        const float* __restrict__ es, const float* __restrict__ ed,
        const __half* __restrict__ hs,
        int d, int lane, int h, float& den, float* a) {
    int start = __ldg(&off[d]), end = __ldg(&off[d + 1]);
    float2 edv = __ldg((const float2*)(ed + d * 8 + h * 2));
    float E1d = edv.x, E2d = edv.y;
    int i = start;
    for (; i + 4 <= end; i += 4) {
        int s0 = __ldg(&srt[i + 0]);
        int s1 = __ldg(&srt[i + 1]);
        int s2 = __ldg(&srt[i + 2]);
        int s3 = __ldg(&srt[i + 3]);
        float2 v0 = __ldg((const float2*)(es + s0 * 8 + h * 2));
        float2 v1 = __ldg((const float2*)(es + s1 * 8 + h * 2));
        float2 v2 = __ldg((const float2*)(es + s2 * 8 + h * 2));
        float2 v3 = __ldg((const float2*)(es + s3 * 8 + h * 2));
        float ee0 = fmaxf(v0.x * E1d, v0.y * E2d);
        float ee1 = fmaxf(v1.x * E1d, v1.y * E2d);
        float ee2 = fmaxf(v2.x * E1d, v2.y * E2d);
        float ee3 = fmaxf(v3.x * E1d, v3.y * E2d);
        den += (ee0 + ee1) + (ee2 + ee3);
        if (D == 128) {
            union { uint2 u; __half2 h2[2]; } c0, c1, c2, c3;
            c0.u = *(const uint2*)(hs + (size_t)s0 * D + lane * 4);
            c1.u = *(const uint2*)(hs + (size_t)s1 * D + lane * 4);
            c2.u = *(const uint2*)(hs + (size_t)s2 * D + lane * 4);
            c3.u = *(const uint2*)(hs + (size_t)s3 * D + lane * 4);
            float2 p;
            p = __half22float2(c0.h2[0]); a[0] += ee0 * p.x; a[1] += ee0 * p.y;
            p = __half22float2(c0.h2[1]); a[2] += ee0 * p.x; a[3] += ee0 * p.y;
            p = __half22float2(c1.h2[0]); a[0] += ee1 * p.x; a[1] += ee1 * p.y;
            p = __half22float2(c1.h2[1]); a[2] += ee1 * p.x; a[3] += ee1 * p.y;
            p = __half22float2(c2.h2[0]); a[0] += ee2 * p.x; a[1] += ee2 * p.y;
            p = __half22float2(c2.h2[1]); a[2] += ee2 * p.x; a[3] += ee2 * p.y;
            p = __half22float2(c3.h2[0]); a[0] += ee3 * p.x; a[1] += ee3 * p.y;
            p = __half22float2(c3.h2[1]); a[2] += ee3 * p.x; a[3] += ee3 * p.y;
        } else {
            union { unsigned u; __half2 h2; } c0, c1, c2, c3;
            c0.u = *(const unsigned*)(hs + (size_t)s0 * D + lane * 2);
            c1.u = *(const unsigned*)(hs + (size_t)s1 * D + lane * 2);
            c2.u = *(const unsigned*)(hs + (size_t)s2 * D + lane * 2);
            c3.u = *(const unsigned*)(hs + (size_t)s3 * D + lane * 2);
            float2 p;
            p = __half22float2(c0.h2); a[0] += ee0 * p.x; a[1] += ee0 * p.y;
            p = __half22float2(c1.h2); a[0] += ee1 * p.x; a[1] += ee1 * p.y;
            p = __half22float2(c2.h2); a[0] += ee2 * p.x; a[1] += ee2 * p.y;
            p = __half22float2(c3.h2); a[0] += ee3 * p.x; a[1] += ee3 * p.y;
        }
    }
    for (; i < end; i++) {
        int s = __ldg(&srt[i]);
        float2 v = __ldg((const float2*)(es + s * 8 + h * 2));
        float ee = fmaxf(v.x * E1d, v.y * E2d);
        den += ee;
        if (D == 128) {
            union { uint2 u; __half2 h2[2]; } cv;
            cv.u = *(const uint2*)(hs + (size_t)s * D + lane * 4);
            float2 p0 = __half22float2(cv.h2[0]), p1 = __half22float2(cv.h2[1]);
            a[0] += ee * p0.x; a[1] += ee * p0.y; a[2] += ee * p1.x; a[3] += ee * p1.y;
        } else {
            union { unsigned u; __half2 h2; } cv;
            cv.u = *(const unsigned*)(hs + (size_t)s * D + lane * 2);
            float2 p = __half22float2(cv.h2);
            a[0] += ee * p.x; a[1] += ee * p.y;
        }
    }
}

// -------- merged gather: TWO relations into one dst write ----------------------
template <int D>
__global__ void __launch_bounds__(256)
gat_gather2(const int* __restrict__ offA, const int* __restrict__ srtA,
            const float* __restrict__ esA, const float* __restrict__ edA,
            const __half* __restrict__ hsA,
            const int* __restrict__ offB, const int* __restrict__ srtB,
            const float* __restrict__ esB, const float* __restrict__ edB,
            const __half* __restrict__ hsB,
            float* __restrict__ acc, int Nd,
            const float* __restrict__ bias0, const float* __restrict__ bias1,
            int relu) {
    constexpr int CPL = D / 32;
    int warp = (blockIdx.x * blockDim.x + threadIdx.x) >> 5;
    int lane = threadIdx.x & 31;
    if (warp >= Nd) return;
    int h = lane >> 3;
    float denA = 0.f, denB = 0.f;
    float aA[4] = {0.f, 0.f, 0.f, 0.f}, aB[4] = {0.f, 0.f, 0.f, 0.f};
    edge_accum<D>(offA, srtA, esA, edA, hsA, warp, lane, h, denA, aA);
    edge_accum<D>(offB, srtB, esB, edB, hsB, warp, lane, h, denB, aB);
    float invA = 1.f / (denA + 1e-16f);
    float invB = 1.f / (denB + 1e-16f);
    int cb = lane * CPL;
    float* dp = acc + (size_t)warp * D + cb;
    if (D == 128) {
        float4 b0 = *(const float4*)(bias0 + cb);
        float4 b1 = *(const float4*)(bias1 + cb);
        float4 o = make_float4(aA[0] * invA + aB[0] * invB + b0.x + b1.x,
                               aA[1] * invA + aB[1] * invB + b0.y + b1.y,
                               aA[2] * invA + aB[2] * invB + b0.z + b1.z,
                               aA[3] * invA + aB[3] * invB + b0.w + b1.w);
        if (relu) {
            o.x = fmaxf(o.x, 0.f); o.y = fmaxf(o.y, 0.f);
            o.z = fmaxf(o.z, 0.f); o.w = fmaxf(o.w, 0.f);
        }
        *(float4*)dp = o;
    } else {
        float2 b0 = *(const float2*)(bias0 + cb);
        float2 b1 = *(const float2*)(bias1 + cb);
        float2 o = make_float2(aA[0] * invA + aB[0] * invB + b0.x + b1.x,
                               aA[1] * invA + aB[1] * invB + b0.y + b1.y);
        if (relu) { o.x = fmaxf(o.x, 0.f); o.y = fmaxf(o.y, 0.f); }
        *(float2*)dp = o;
    }
}

// -------- single-relation gather -----------------------------------------------
template <int D>
__global__ void __launch_bounds__(256)
gat_gather1(const int* __restrict__ off, const int* __restrict__ srt,
            const float* __restrict__ es, const float* __restrict__ ed,
            const __half* __restrict__ hs,
            float* __restrict__ acc, int Nd,
            const float* __restrict__ bias0, int relu) {
    constexpr int CPL = D / 32;
    int warp = (blockIdx.x * blockDim.x + threadIdx.x) >> 5;
    int lane = threadIdx.x & 31;
    if (warp >= Nd) return;
    int h = lane >> 3;
    float den = 0.f;
    float a[4] = {0.f, 0.f, 0.f, 0.f};
    edge_accum<D>(off, srt, es, ed, hs, warp, lane, h, den, a);
    float inv = 1.f / (den + 1e-16f);
    int cb = lane * CPL;
    float* dp = acc + (size_t)warp * D + cb;
    if (D == 128) {
        float4 b0 = *(const float4*)(bias0 + cb);
        float4 o = make_float4(a[0] * inv + b0.x, a[1] * inv + b0.y,
                               a[2] * inv + b0.z, a[3] * inv + b0.w);
        if (relu) {
            o.x = fmaxf(o.x, 0.f); o.y = fmaxf(o.y, 0.f);
            o.z = fmaxf(o.z, 0.f); o.w = fmaxf(o.w, 0.f);
        }
        *(float4*)dp = o;
    } else {
        float2 b0 = *(const float2*)(bias0 + cb);
        float2 o = make_float2(a[0] * inv + b0.x, a[1] * inv + b0.y);
        if (relu) { o.x = fmaxf(o.x, 0.f); o.y = fmaxf(o.y, 0.f); }
        *(float2*)dp = o;
    }
}

// =============================================================================
extern "C" void kernel_launch(void* const* d_in, const int* in_sizes, int n_in,
                              void* d_out, int out_size) {
    const float* x_p = (const float*)d_in[0];
    const float* x_a = (const float*)d_in[1];
    const int* src_pp = (const int*)d_in[2];
    const int* dst_pp = (const int*)d_in[3];
    const int* src_ap = (const int*)d_in[4];
    const int* dst_ap = (const int*)d_in[5];
    const int* src_pa = (const int*)d_in[6];
    const int* dst_pa = (const int*)d_in[7];
    const float* Wsrc1 = (const float*)d_in[8];
    const float* Wdst1 = (const float*)d_in[9];
    const float* asrc1 = (const float*)d_in[10];
    const float* adst1 = (const float*)d_in[11];
    const float* b1 = (const float*)d_in[12];
    const float* Wsrc2 = (const float*)d_in[13];
    const float* Wdst2 = (const float*)d_in[14];
    const float* asrc2 = (const float*)d_in[15];
    const float* adst2 = (const float*)d_in[16];
    const float* b2 = (const float*)d_in[17];
    float* out = (float*)d_out;

    void* p;
    cudaGetSymbolAddress(&p, g_hs0);    __half* hs0 = (__half*)p;
    cudaGetSymbolAddress(&p, g_hs1);    __half* hs1 = (__half*)p;
    cudaGetSymbolAddress(&p, g_hs2);    __half* hs2 = (__half*)p;
    cudaGetSymbolAddress(&p, g_es);     float* es   = (float*)p;
    cudaGetSymbolAddress(&p, g_ed);     float* ed   = (float*)p;
    cudaGetSymbolAddress(&p, g_accp);   float* accp = (float*)p;
    cudaGetSymbolAddress(&p, g_acca);   float* acca = (float*)p;
    cudaGetSymbolAddress(&p, g_vd1);    float* vd1  = (float*)p;
    cudaGetSymbolAddress(&p, g_vd2);    float* vd2  = (float*)p;
    cudaGetSymbolAddress(&p, g_off_pp); int* off_pp = (int*)p;
    cudaGetSymbolAddress(&p, g_off_ap); int* off_ap = (int*)p;
    cudaGetSymbolAddress(&p, g_off_pa); int* off_pa = (int*)p;
    cudaGetSymbolAddress(&p, g_srt);    int* srt    = (int*)p;
    cudaGetSymbolAddress(&p, g_writer); int* writer = (int*)p;

    int* srt_pp = srt;
    int* srt_ap = srt + EPP;
    int* srt_pa = srt + EPP + EAP;

    float* es0 = es;
    float* es1 = es + NP * 8;
    float* es2 = es + 2 * NP * 8;
    float* ed0 = ed;
    float* ed1 = ed + NP * 8;
    float* ed2 = ed + 2 * NP * 8;

    const int TB = 256;
    auto blocks = [](long long n) { return (int)((n + 255) / 256); };

    // ---- batched CSR build (reused by both layers) ----
    zero3<<<blocks((NP + 1) + (NP + 1) + (NA + 1)), TB>>>(off_pp, NP + 1, off_ap, NP + 1,
                                                          off_pa, NA + 1);
    count3<<<blocks(EPP + EAP + EPA), TB>>>(dst_pp, dst_ap, dst_pa, off_pp, off_ap, off_pa);
    scan3<<<3, 1024>>>(off_pp, off_ap, off_pa, writer);
    scatter3<<<blocks(EPP + EAP + EPA), TB>>>(src_pp, dst_pp, src_ap, dst_ap,
                                              src_pa, dst_pa, writer, srt);

    compute_vd<<<blocks(2 * 3 * 128 * 4), TB>>>(Wdst1, adst1, Wdst2, adst2, vd1, vd2);

    // ---------------- layer 1 (D=128) ----------------
    {
        dim3 gP(2, (NP + 127) / 128), gA(2, (NA + 127) / 128);
        mma_es<32, 2><<<gP, 256>>>(x_p, Wsrc1 + 0 * 128 * 128, hs0, es0, asrc1 + 0 * 128,
                                   vd1 + 0 * 512, vd1 + 1 * 512, ed0, ed1, NP, 128);
        mma_es<32, 1><<<gA, 256>>>(x_a, Wsrc1 + 1 * 128 * 128, hs1, es1, asrc1 + 1 * 128,
                                   vd1 + 2 * 512, nullptr, ed2, nullptr, NA, 128);
        mma_es<32, 0><<<gP, 256>>>(x_p, Wsrc1 + 2 * 128 * 128, hs2, es2, asrc1 + 2 * 128,
                                   nullptr, nullptr, nullptr, nullptr, NP, 128);
        gat_gather2<128><<<blocks((long long)NP * 32), TB>>>(
            off_pp, srt_pp, es0, ed0, hs0, off_ap, srt_ap, es1, ed1, hs1,
            accp, NP, b1 + 0, b1 + 128, 1);
        gat_gather1<128><<<blocks((long long)NA * 32), TB>>>(
            off_pa, srt_pa, es2, ed2, hs2, acca, NA, b1 + 256, 1);
    }

    // ---------------- layer 2 (D=64) -> d_out ----------------
    {
        dim3 gP(1, (NP + 127) / 128), gA(1, (NA + 127) / 128);
        mma_es<16, 2><<<gP, 256>>>(accp, Wsrc2 + 0 * 128 * 64, hs0, es0, asrc2 + 0 * 64,
                                   vd2 + 0 * 512, vd2 + 1 * 512, ed0, ed1, NP, 64);
        mma_es<16, 1><<<gA, 256>>>(acca, Wsrc2 + 1 * 128 * 64, hs1, es1, asrc2 + 1 * 64,
                                   vd2 + 2 * 512, nullptr, ed2, nullptr, NA, 64);
        mma_es<16, 0><<<gP, 256>>>(accp, Wsrc2 + 2 * 128 * 64, hs2, es2, asrc2 + 2 * 64,
                                   nullptr, nullptr, nullptr, nullptr, NP, 64);
        gat_gather2<64><<<blocks((long long)NP * 32), TB>>>(
            off_pp, srt_pp, es0, ed0, hs0, off_ap, srt_ap, es1, ed1, hs1,
            out, NP, b2 + 0, b2 + 64, 0);
        gat_gather1<64><<<blocks((long long)NA * 32), TB>>>(
            off_pa, srt_pa, es2, ed2, hs2, out + (size_t)NP * 64, NA, b2 + 128, 0);
    }
}

// round 13
// speedup vs baseline: 2.9944x; 1.0342x over previous
#include <cuda_runtime.h>
#include <cuda_bf16.h>
#include <cuda_fp16.h>
#include <cstdint>

#define NP 100000
#define NA 50000
#define EPP 1600000
#define EAP 800000
#define EPA 800000

// ---------------- scratch ----------------------------------------------------
__device__ __align__(16) __half g_hs0[NP * 128];
__device__ __align__(16) __half g_hs1[NA * 128];
__device__ __align__(16) __half g_hs2[NP * 128];
__device__ __align__(16) float g_es[3 * NP * 8];
__device__ __align__(16) float g_ed[3 * NP * 8];
__device__ __align__(16) float g_accp[NP * 128];
__device__ __align__(16) float g_acca[NA * 128];
__device__ __align__(16) float g_vd1[3 * 512];
__device__ __align__(16) float g_vd2[3 * 512];
// CSR scratch
__device__ int g_off_pp[NP + 1];
__device__ int g_off_ap[NP + 1];
__device__ int g_off_pa[NA + 1];
__device__ int g_srt[EPP + EAP + EPA];
__device__ int g_writer[NP + NP + NA];

// ---------------- helpers ----------------------------------------------------
__device__ __forceinline__ uint32_t tf32(float x) {
    uint32_t r;
    asm("cvt.rna.tf32.f32 %0, %1;" : "=r"(r) : "f"(x));
    return r;
}
__device__ __forceinline__ void mma_tf32(float* d, const uint32_t* a, const uint32_t* b) {
    asm("mma.sync.aligned.m16n8k8.row.col.f32.tf32.tf32.f32 "
        "{%0,%1,%2,%3},{%4,%5,%6,%7},{%8,%9},{%0,%1,%2,%3};"
        : "+f"(d[0]), "+f"(d[1]), "+f"(d[2]), "+f"(d[3])
        : "r"(a[0]), "r"(a[1]), "r"(a[2]), "r"(a[3]), "r"(b[0]), "r"(b[1]));
}

// ---------------- batched CSR build -------------------------------------------
__global__ void zero3(int* __restrict__ a, int na, int* __restrict__ b, int nb,
                      int* __restrict__ c, int nc) {
    int i = blockIdx.x * blockDim.x + threadIdx.x;
    if (i < na) a[i] = 0;
    else if (i < na + nb) b[i - na] = 0;
    else if (i < na + nb + nc) c[i - na - nb] = 0;
}
__global__ void count3(const int* __restrict__ d0, const int* __restrict__ d1,
                       const int* __restrict__ d2, int* __restrict__ o0,
                       int* __restrict__ o1, int* __restrict__ o2) {
    int i = blockIdx.x * blockDim.x + threadIdx.x;
    if (i < EPP) atomicAdd(&o0[d0[i] + 1], 1);
    else if (i < EPP + EAP) atomicAdd(&o1[d1[i - EPP] + 1], 1);
    else if (i < EPP + EAP + EPA) atomicAdd(&o2[d2[i - EPP - EAP] + 1], 1);
}
__device__ void scan_one(int* __restrict__ off, int* __restrict__ writer, int n, int nw) {
    __shared__ int ssum[1024];
    int tid = threadIdx.x;
    int running = 0;
    for (int base = 0; base < n; base += 4096) {
        int idx = base + tid * 4;
        int v0 = idx + 0 < n ? off[idx + 0] : 0;
        int v1 = idx + 1 < n ? off[idx + 1] : 0;
        int v2 = idx + 2 < n ? off[idx + 2] : 0;
        int v3 = idx + 3 < n ? off[idx + 3] : 0;
        int p0 = v0, p1 = p0 + v1, p2 = p1 + v2, p3 = p2 + v3;
        ssum[tid] = p3;
        __syncthreads();
        for (int o = 1; o < 1024; o <<= 1) {
            int val = 0;
            if (tid >= o) val = ssum[tid - o];
            __syncthreads();
            if (tid >= o) ssum[tid] += val;
            __syncthreads();
        }
        int excl = running + (tid ? ssum[tid - 1] : 0);
        int total = ssum[1023];
        __syncthreads();
        int s0 = excl + p0, s1 = excl + p1, s2 = excl + p2, s3 = excl + p3;
        if (idx + 0 < n) { off[idx + 0] = s0; if (idx + 0 < nw) writer[idx + 0] = s0; }
        if (idx + 1 < n) { off[idx + 1] = s1; if (idx + 1 < nw) writer[idx + 1] = s1; }
        if (idx + 2 < n) { off[idx + 2] = s2; if (idx + 2 < nw) writer[idx + 2] = s2; }
        if (idx + 3 < n) { off[idx + 3] = s3; if (idx + 3 < nw) writer[idx + 3] = s3; }
        running += total;
    }
}
__global__ void __launch_bounds__(1024)
scan3(int* __restrict__ o0, int* __restrict__ o1, int* __restrict__ o2,
      int* __restrict__ writer) {
    if (blockIdx.x == 0)      scan_one(o0, writer, NP + 1, NP);
    else if (blockIdx.x == 1) scan_one(o1, writer + NP, NP + 1, NP);
    else                      scan_one(o2, writer + 2 * NP, NA + 1, NA);
}
__global__ void scatter3(const int* __restrict__ s0, const int* __restrict__ d0,
                         const int* __restrict__ s1, const int* __restrict__ d1,
                         const int* __restrict__ s2, const int* __restrict__ d2,
                         int* __restrict__ writer, int* __restrict__ srt) {
    int i = blockIdx.x * blockDim.x + threadIdx.x;
    if (i < EPP) {
        int pos = atomicAdd(&writer[d0[i]], 1);
        srt[pos] = s0[i];
    } else if (i < EPP + EAP) {
        int e = i - EPP;
        int pos = atomicAdd(&writer[NP + d1[e]], 1);
        srt[EPP + pos] = s1[e];
    } else if (i < EPP + EAP + EPA) {
        int e = i - EPP - EAP;
        int pos = atomicAdd(&writer[2 * NP + d2[e]], 1);
        srt[EPP + EAP + pos] = s2[e];
    }
}

// ---------------- vd folding ---------------------------------------------------
__global__ void compute_vd(const float* __restrict__ Wd1, const float* __restrict__ ad1,
                           const float* __restrict__ Wd2, const float* __restrict__ ad2,
                           float* __restrict__ vd1, float* __restrict__ vd2) {
    int i = blockIdx.x * blockDim.x + threadIdx.x;
    if (i >= 2 * 3 * 128 * 4) return;
    int layer = i >= 3 * 128 * 4;
    int ii = i - layer * 3 * 128 * 4;
    int h = ii & 3;
    int f = (ii >> 2) & 127;
    int r = ii >> 9;
    int D = layer ? 64 : 128;
    int C = D / 4;
    const float* W = (layer ? Wd2 : Wd1) + (size_t)r * 128 * D + (size_t)f * D + h * C;
    const float* a = (layer ? ad2 : ad1) + r * 4 * C + h * C;
    float s = 0.f;
    for (int c = 0; c < C; c++) s += W[c] * a[c];
    (layer ? vd2 : vd1)[r * 512 + f * 4 + h] = s;
}

// ---------------- tf32 MMA GEMM + es epilogue + fused ed -----------------------
template <int CC, int NED>
__global__ void __launch_bounds__(256)
mma_es(const float* __restrict__ A, const float* __restrict__ B,
       __half* __restrict__ C, float* __restrict__ es,
       const float* __restrict__ a_s,
       const float* __restrict__ vdA, const float* __restrict__ vdB,
       float* __restrict__ edA, float* __restrict__ edB,
       int M, int N) {
    const int K = 128;
    const int BKc = 16;
    __shared__ __align__(16) float As[2][128][BKc + 4];
    __shared__ __align__(16) float Bs[2][BKc][64 + 8];
    __shared__ __align__(16) float vds[128][8];
    int tid = threadIdx.x;
    int lane = tid & 31, wid = tid >> 5;
    int wm = wid & 3, wn = wid >> 2;
    int g = lane >> 2, tig = lane & 3;
    int m0 = blockIdx.y * 128, n0 = blockIdx.x * 64;

    if (NED > 0) {
        for (int i = tid; i < 1024; i += 256) {
            int k = i >> 3, j = i & 7;
            float v = 0.f;
            if (j < 4) v = vdA[k * 4 + j];
            else if (NED == 2) v = vdB[k * 4 + (j - 4)];
            vds[k][j] = v;
        }
    }

    float cfr[2][4][4];
#pragma unroll
    for (int mt = 0; mt < 2; mt++)
#pragma unroll
        for (int nt = 0; nt < 4; nt++)
#pragma unroll
            for (int q = 0; q < 4; q++) cfr[mt][nt][q] = 0.f;
    float edf[2][4];
#pragma unroll
    for (int mt = 0; mt < 2; mt++)
#pragma unroll
        for (int q = 0; q < 4; q++) edf[mt][q] = 0.f;
    bool do_ed = (NED > 0) && (wn == 0) && (blockIdx.x == 0);

    int aRow = tid >> 1, aK = (tid & 1) * 8;
    int bRow = tid >> 4, bC = (tid & 15) * 4;

    float4 ra0, ra1, rb;
    auto loadg = [&](int k0) {
        int m = m0 + aRow;
        if (m < M) {
            ra0 = *(const float4*)(A + (size_t)m * K + k0 + aK);
            ra1 = *(const float4*)(A + (size_t)m * K + k0 + aK + 4);
        } else {
            ra0 = make_float4(0.f, 0.f, 0.f, 0.f);
            ra1 = ra0;
        }
        rb = *(const float4*)(B + (size_t)(k0 + bRow) * N + n0 + bC);
    };
    auto stores = [&](int buf) {
        *(float4*)&As[buf][aRow][aK] = ra0;
        *(float4*)&As[buf][aRow][aK + 4] = ra1;
        *(float4*)&Bs[buf][bRow][bC] = rb;
    };

    loadg(0);
    stores(0);
    __syncthreads();

#pragma unroll 1
    for (int c = 0; c < 8; c++) {
        if (c + 1 < 8) loadg((c + 1) * BKc);
        int buf = c & 1;
#pragma unroll
        for (int kk = 0; kk < BKc; kk += 8) {
            uint32_t af[2][4], bf[4][2];
#pragma unroll
            for (int mt = 0; mt < 2; mt++) {
                int rm = wm * 32 + mt * 16;
                af[mt][0] = tf32(As[buf][rm + g][kk + tig]);
                af[mt][1] = tf32(As[buf][rm + g + 8][kk + tig]);
                af[mt][2] = tf32(As[buf][rm + g][kk + tig + 4]);
                af[mt][3] = tf32(As[buf][rm + g + 8][kk + tig + 4]);
            }
#pragma unroll
            for (int nt = 0; nt < 4; nt++) {
                int cn = wn * 32 + nt * 8;
                bf[nt][0] = tf32(Bs[buf][kk + tig][cn + g]);
                bf[nt][1] = tf32(Bs[buf][kk + tig + 4][cn + g]);
            }
#pragma unroll
            for (int mt = 0; mt < 2; mt++)
#pragma unroll
                for (int nt = 0; nt < 4; nt++)
                    mma_tf32(cfr[mt][nt], af[mt], bf[nt]);
            if (do_ed) {
                uint32_t bvd[2];
                int kg = c * BKc + kk;
                bvd[0] = tf32(vds[kg + tig][g]);
                bvd[1] = tf32(vds[kg + tig + 4][g]);
                mma_tf32(edf[0], af[0], bvd);
                mma_tf32(edf[1], af[1], bvd);
            }
        }
        if (c + 1 < 8) stores((c + 1) & 1);
        __syncthreads();
    }

    if (do_ed) {
        auto edst = [&](int m, int col, float v) {
            int rel = col >> 2;
            if (rel == 1 && NED < 2) return;
            int h = col & 3;
            float* dst = rel ? edB : edA;
            if (m < M)
                *(float2*)(dst + m * 8 + h * 2) =
                    make_float2(__expf(v), __expf(0.2f * v));
        };
#pragma unroll
        for (int mt = 0; mt < 2; mt++) {
            int m_lo = m0 + wm * 32 + mt * 16 + g;
            int m_hi = m_lo + 8;
            edst(m_lo, 2 * tig + 0, edf[mt][0]);
            edst(m_lo, 2 * tig + 1, edf[mt][1]);
            edst(m_hi, 2 * tig + 0, edf[mt][2]);
            edst(m_hi, 2 * tig + 1, edf[mt][3]);
        }
    }

    {
        constexpr int NH = 32 / CC;
        float pl[2][NH], ph[2][NH];
#pragma unroll
        for (int mt = 0; mt < 2; mt++)
#pragma unroll
            for (int nh = 0; nh < NH; nh++) { pl[mt][nh] = 0.f; ph[mt][nh] = 0.f; }
#pragma unroll
        for (int nt = 0; nt < 4; nt++) {
            int nh = (nt * 8) / CC;
            float w0 = __ldg(&a_s[n0 + wn * 32 + nt * 8 + 2 * tig]);
            float w1 = __ldg(&a_s[n0 + wn * 32 + nt * 8 + 2 * tig + 1]);
#pragma unroll
            for (int mt = 0; mt < 2; mt++) {
                pl[mt][nh] += cfr[mt][nt][0] * w0 + cfr[mt][nt][1] * w1;
                ph[mt][nh] += cfr[mt][nt][2] * w0 + cfr[mt][nt][3] * w1;
            }
        }
#pragma unroll
        for (int mt = 0; mt < 2; mt++)
#pragma unroll
            for (int nh = 0; nh < NH; nh++) {
#pragma unroll
                for (int off = 1; off < 4; off <<= 1) {
                    pl[mt][nh] += __shfl_xor_sync(0xffffffffu, pl[mt][nh], off, 4);
                    ph[mt][nh] += __shfl_xor_sync(0xffffffffu, ph[mt][nh], off, 4);
                }
                if (tig == 0) {
                    int h = (n0 + wn * 32) / CC + nh;
                    int m_lo = m0 + wm * 32 + mt * 16 + g;
                    int m_hi = m_lo + 8;
                    if (m_lo < M)
                        *(float2*)(es + m_lo * 8 + h * 2) =
                            make_float2(__expf(pl[mt][nh]), __expf(0.2f * pl[mt][nh]));
                    if (m_hi < M)
                        *(float2*)(es + m_hi * 8 + h * 2) =
                            make_float2(__expf(ph[mt][nh]), __expf(0.2f * ph[mt][nh]));
                }
            }
    }

#pragma unroll
    for (int mt = 0; mt < 2; mt++) {
        int m_lo = m0 + wm * 32 + mt * 16 + g;
        int m_hi = m_lo + 8;
#pragma unroll
        for (int nt = 0; nt < 4; nt++) {
            int col = n0 + wn * 32 + nt * 8 + 2 * tig;
            if (m_lo < M)
                *(__half2*)(C + (size_t)m_lo * N + col) =
                    __floats2half2_rn(cfr[mt][nt][0], cfr[mt][nt][1]);
            if (m_hi < M)
                *(__half2*)(C + (size_t)m_hi * N + col) =
                    __floats2half2_rn(cfr[mt][nt][2], cfr[mt][nt][3]);
        }
    }
}

// -------- per-relation edge accumulation, unroll-8 for MLP ---------------------
template <int D>
__device__ __forceinline__ void edge_accum(
        const int* __restrict__ off, const int* __restrict__ srt,
        const float* __restrict__ es, const float* __restrict__ ed,
        const __half* __restrict__ hs,
        int d, int lane, int h, float& den, float* a) {
    int start = __ldg(&off[d]), end = __ldg(&off[d + 1]);
    float2 edv = __ldg((const float2*)(ed + d * 8 + h * 2));
    float E1d = edv.x, E2d = edv.y;
    int i = start;
    for (; i + 8 <= end; i += 8) {
        int s[8];
#pragma unroll
        for (int j = 0; j < 8; j++) s[j] = __ldg(&srt[i + j]);
        float2 v[8];
#pragma unroll
        for (int j = 0; j < 8; j++)
            v[j] = __ldg((const float2*)(es + s[j] * 8 + h * 2));
        if (D == 128) {
            uint2 u[8];
#pragma unroll
            for (int j = 0; j < 8; j++)
                u[j] = *(const uint2*)(hs + (size_t)s[j] * D + lane * 4);
#pragma unroll
            for (int j = 0; j < 8; j++) {
                float ee = fmaxf(v[j].x * E1d, v[j].y * E2d);
                den += ee;
                union { uint2 uu; __half2 h2[2]; } cv;
                cv.uu = u[j];
                float2 p0 = __half22float2(cv.h2[0]);
                float2 p1 = __half22float2(cv.h2[1]);
                a[0] += ee * p0.x; a[1] += ee * p0.y;
                a[2] += ee * p1.x; a[3] += ee * p1.y;
            }
        } else {
            unsigned u[8];
#pragma unroll
            for (int j = 0; j < 8; j++)
                u[j] = *(const unsigned*)(hs + (size_t)s[j] * D + lane * 2);
#pragma unroll
            for (int j = 0; j < 8; j++) {
                float ee = fmaxf(v[j].x * E1d, v[j].y * E2d);
                den += ee;
                union { unsigned uu; __half2 h2; } cv;
                cv.uu = u[j];
                float2 p = __half22float2(cv.h2);
                a[0] += ee * p.x; a[1] += ee * p.y;
            }
        }
    }
    for (; i < end; i++) {
        int s = __ldg(&srt[i]);
        float2 v = __ldg((const float2*)(es + s * 8 + h * 2));
        float ee = fmaxf(v.x * E1d, v.y * E2d);
        den += ee;
        if (D == 128) {
            union { uint2 u; __half2 h2[2]; } cv;
            cv.u = *(const uint2*)(hs + (size_t)s * D + lane * 4);
            float2 p0 = __half22float2(cv.h2[0]), p1 = __half22float2(cv.h2[1]);
            a[0] += ee * p0.x; a[1] += ee * p0.y; a[2] += ee * p1.x; a[3] += ee * p1.y;
        } else {
            union { unsigned u; __half2 h2; } cv;
            cv.u = *(const unsigned*)(hs + (size_t)s * D + lane * 2);
            float2 p = __half22float2(cv.h2);
            a[0] += ee * p.x; a[1] += ee * p.y;
        }
    }
}

// -------- SINGLE gather over all dst nodes (paper: pp+ap; author: pa) ----------
template <int D>
__global__ void __launch_bounds__(256)
gat_gather_all(const int* __restrict__ off0, const int* __restrict__ srt0,
               const float* __restrict__ es0, const float* __restrict__ ed0,
               const __half* __restrict__ hs0,
               const int* __restrict__ off1, const int* __restrict__ srt1,
               const float* __restrict__ es1, const float* __restrict__ ed1,
               const __half* __restrict__ hs1,
               const int* __restrict__ off2, const int* __restrict__ srt2,
               const float* __restrict__ es2, const float* __restrict__ ed2,
               const __half* __restrict__ hs2,
               float* __restrict__ accP, float* __restrict__ accA,
               const float* __restrict__ bP0, const float* __restrict__ bP1,
               const float* __restrict__ bA0, int relu) {
    constexpr int CPL = D / 32;
    int warp = (blockIdx.x * blockDim.x + threadIdx.x) >> 5;
    int lane = threadIdx.x & 31;
    int h = lane >> 3;
    int cb = lane * CPL;
    if (warp < NP) {
        int d = warp;
        float denA = 0.f, denB = 0.f;
        float aA[4] = {0.f, 0.f, 0.f, 0.f}, aB[4] = {0.f, 0.f, 0.f, 0.f};
        edge_accum<D>(off0, srt0, es0, ed0, hs0, d, lane, h, denA, aA);
        edge_accum<D>(off1, srt1, es1, ed1, hs1, d, lane, h, denB, aB);
        float invA = 1.f / (denA + 1e-16f);
        float invB = 1.f / (denB + 1e-16f);
        float* dp = accP + (size_t)d * D + cb;
        if (D == 128) {
            float4 b0 = *(const float4*)(bP0 + cb);
            float4 b1 = *(const float4*)(bP1 + cb);
            float4 o = make_float4(aA[0] * invA + aB[0] * invB + b0.x + b1.x,
                                   aA[1] * invA + aB[1] * invB + b0.y + b1.y,
                                   aA[2] * invA + aB[2] * invB + b0.z + b1.z,
                                   aA[3] * invA + aB[3] * invB + b0.w + b1.w);
            if (relu) {
                o.x = fmaxf(o.x, 0.f); o.y = fmaxf(o.y, 0.f);
                o.z = fmaxf(o.z, 0.f); o.w = fmaxf(o.w, 0.f);
            }
            *(float4*)dp = o;
        } else {
            float2 b0 = *(const float2*)(bP0 + cb);
            float2 b1 = *(const float2*)(bP1 + cb);
            float2 o = make_float2(aA[0] * invA + aB[0] * invB + b0.x + b1.x,
                                   aA[1] * invA + aB[1] * invB + b0.y + b1.y);
            if (relu) { o.x = fmaxf(o.x, 0.f); o.y = fmaxf(o.y, 0.f); }
            *(float2*)dp = o;
        }
    } else if (warp < NP + NA) {
        int d = warp - NP;
        float den = 0.f;
        float a[4] = {0.f, 0.f, 0.f, 0.f};
        edge_accum<D>(off2, srt2, es2, ed2, hs2, d, lane, h, den, a);
        float inv = 1.f / (den + 1e-16f);
        float* dp = accA + (size_t)d * D + cb;
        if (D == 128) {
            float4 b0 = *(const float4*)(bA0 + cb);
            float4 o = make_float4(a[0] * inv + b0.x, a[1] * inv + b0.y,
                                   a[2] * inv + b0.z, a[3] * inv + b0.w);
            if (relu) {
                o.x = fmaxf(o.x, 0.f); o.y = fmaxf(o.y, 0.f);
                o.z = fmaxf(o.z, 0.f); o.w = fmaxf(o.w, 0.f);
            }
            *(float4*)dp = o;
        } else {
            float2 b0 = *(const float2*)(bA0 + cb);
            float2 o = make_float2(a[0] * inv + b0.x, a[1] * inv + b0.y);
            if (relu) { o.x = fmaxf(o.x, 0.f); o.y = fmaxf(o.y, 0.f); }
            *(float2*)dp = o;
        }
    }
}

// =============================================================================
extern "C" void kernel_launch(void* const* d_in, const int* in_sizes, int n_in,
                              void* d_out, int out_size) {
    const float* x_p = (const float*)d_in[0];
    const float* x_a = (const float*)d_in[1];
    const int* src_pp = (const int*)d_in[2];
    const int* dst_pp = (const int*)d_in[3];
    const int* src_ap = (const int*)d_in[4];
    const int* dst_ap = (const int*)d_in[5];
    const int* src_pa = (const int*)d_in[6];
    const int* dst_pa = (const int*)d_in[7];
    const float* Wsrc1 = (const float*)d_in[8];
    const float* Wdst1 = (const float*)d_in[9];
    const float* asrc1 = (const float*)d_in[10];
    const float* adst1 = (const float*)d_in[11];
    const float* b1 = (const float*)d_in[12];
    const float* Wsrc2 = (const float*)d_in[13];
    const float* Wdst2 = (const float*)d_in[14];
    const float* asrc2 = (const float*)d_in[15];
    const float* adst2 = (const float*)d_in[16];
    const float* b2 = (const float*)d_in[17];
    float* out = (float*)d_out;

    void* p;
    cudaGetSymbolAddress(&p, g_hs0);    __half* hs0 = (__half*)p;
    cudaGetSymbolAddress(&p, g_hs1);    __half* hs1 = (__half*)p;
    cudaGetSymbolAddress(&p, g_hs2);    __half* hs2 = (__half*)p;
    cudaGetSymbolAddress(&p, g_es);     float* es   = (float*)p;
    cudaGetSymbolAddress(&p, g_ed);     float* ed   = (float*)p;
    cudaGetSymbolAddress(&p, g_accp);   float* accp = (float*)p;
    cudaGetSymbolAddress(&p, g_acca);   float* acca = (float*)p;
    cudaGetSymbolAddress(&p, g_vd1);    float* vd1  = (float*)p;
    cudaGetSymbolAddress(&p, g_vd2);    float* vd2  = (float*)p;
    cudaGetSymbolAddress(&p, g_off_pp); int* off_pp = (int*)p;
    cudaGetSymbolAddress(&p, g_off_ap); int* off_ap = (int*)p;
    cudaGetSymbolAddress(&p, g_off_pa); int* off_pa = (int*)p;
    cudaGetSymbolAddress(&p, g_srt);    int* srt    = (int*)p;
    cudaGetSymbolAddress(&p, g_writer); int* writer = (int*)p;

    int* srt_pp = srt;
    int* srt_ap = srt + EPP;
    int* srt_pa = srt + EPP + EAP;

    float* es0 = es;
    float* es1 = es + NP * 8;
    float* es2 = es + 2 * NP * 8;
    float* ed0 = ed;
    float* ed1 = ed + NP * 8;
    float* ed2 = ed + 2 * NP * 8;

    const int TB = 256;
    auto blocks = [](long long n) { return (int)((n + 255) / 256); };

    // ---- batched CSR build (reused by both layers) ----
    zero3<<<blocks((NP + 1) + (NP + 1) + (NA + 1)), TB>>>(off_pp, NP + 1, off_ap, NP + 1,
                                                          off_pa, NA + 1);
    count3<<<blocks(EPP + EAP + EPA), TB>>>(dst_pp, dst_ap, dst_pa, off_pp, off_ap, off_pa);
    scan3<<<3, 1024>>>(off_pp, off_ap, off_pa, writer);
    scatter3<<<blocks(EPP + EAP + EPA), TB>>>(src_pp, dst_pp, src_ap, dst_ap,
                                              src_pa, dst_pa, writer, srt);

    compute_vd<<<blocks(2 * 3 * 128 * 4), TB>>>(Wdst1, adst1, Wdst2, adst2, vd1, vd2);

    // ---------------- layer 1 (D=128) ----------------
    {
        dim3 gP(2, (NP + 127) / 128), gA(2, (NA + 127) / 128);
        mma_es<32, 2><<<gP, 256>>>(x_p, Wsrc1 + 0 * 128 * 128, hs0, es0, asrc1 + 0 * 128,
                                   vd1 + 0 * 512, vd1 + 1 * 512, ed0, ed1, NP, 128);
        mma_es<32, 1><<<gA, 256>>>(x_a, Wsrc1 + 1 * 128 * 128, hs1, es1, asrc1 + 1 * 128,
                                   vd1 + 2 * 512, nullptr, ed2, nullptr, NA, 128);
        mma_es<32, 0><<<gP, 256>>>(x_p, Wsrc1 + 2 * 128 * 128, hs2, es2, asrc1 + 2 * 128,
                                   nullptr, nullptr, nullptr, nullptr, NP, 128);
        gat_gather_all<128><<<blocks((long long)(NP + NA) * 32), TB>>>(
            off_pp, srt_pp, es0, ed0, hs0,
            off_ap, srt_ap, es1, ed1, hs1,
            off_pa, srt_pa, es2, ed2, hs2,
            accp, acca, b1 + 0, b1 + 128, b1 + 256, 1);
    }

    // ---------------- layer 2 (D=64) -> d_out ----------------
    {
        dim3 gP(1, (NP + 127) / 128), gA(1, (NA + 127) / 128);
        mma_es<16, 2><<<gP, 256>>>(accp, Wsrc2 + 0 * 128 * 64, hs0, es0, asrc2 + 0 * 64,
                                   vd2 + 0 * 512, vd2 + 1 * 512, ed0, ed1, NP, 64);
        mma_es<16, 1><<<gA, 256>>>(acca, Wsrc2 + 1 * 128 * 64, hs1, es1, asrc2 + 1 * 64,
                                   vd2 + 2 * 512, nullptr, ed2, nullptr, NA, 64);
        mma_es<16, 0><<<gP, 256>>>(accp, Wsrc2 + 2 * 128 * 64, hs2, es2, asrc2 + 2 * 64,
                                   nullptr, nullptr, nullptr, nullptr, NP, 64);
        gat_gather_all<64><<<blocks((long long)(NP + NA) * 32), TB>>>(
            off_pp, srt_pp, es0, ed0, hs0,
            off_ap, srt_ap, es1, ed1, hs1,
            off_pa, srt_pa, es2, ed2, hs2,
            out, out + (size_t)NP * 64, b2 + 0, b2 + 64, b2 + 128, 0);
    }
}

// round 14
// speedup vs baseline: 3.0802x; 1.0287x over previous
#include <cuda_runtime.h>
#include <cuda_bf16.h>
#include <cuda_fp16.h>
#include <cstdint>

#define NP 100000
#define NA 50000
#define EPP 1600000
#define EAP 800000
#define EPA 800000

// ---------------- scratch ----------------------------------------------------
__device__ __align__(16) __half g_hs0[NP * 128];
__device__ __align__(16) __half g_hs1[NA * 128];
__device__ __align__(16) __half g_hs2[NP * 128];
__device__ __align__(16) float g_es[3 * NP * 8];
__device__ __align__(16) float g_ed[3 * NP * 8];
__device__ __align__(16) float g_accp[NP * 128];
__device__ __align__(16) float g_acca[NA * 128];
__device__ __align__(16) float g_vd1[3 * 512];
__device__ __align__(16) float g_vd2[3 * 512];
// CSR scratch
__device__ int g_off_pp[NP + 1];
__device__ int g_off_ap[NP + 1];
__device__ int g_off_pa[NA + 1];
__device__ int g_srt[EPP + EAP + EPA];
__device__ int g_writer[NP + NP + NA];

// ---------------- helpers ----------------------------------------------------
__device__ __forceinline__ uint32_t tf32(float x) {
    uint32_t r;
    asm("cvt.rna.tf32.f32 %0, %1;" : "=r"(r) : "f"(x));
    return r;
}
__device__ __forceinline__ void mma_tf32(float* d, const uint32_t* a, const uint32_t* b) {
    asm("mma.sync.aligned.m16n8k8.row.col.f32.tf32.tf32.f32 "
        "{%0,%1,%2,%3},{%4,%5,%6,%7},{%8,%9},{%0,%1,%2,%3};"
        : "+f"(d[0]), "+f"(d[1]), "+f"(d[2]), "+f"(d[3])
        : "r"(a[0]), "r"(a[1]), "r"(a[2]), "r"(a[3]), "r"(b[0]), "r"(b[1]));
}

// ---------------- batched CSR build -------------------------------------------
__global__ void count3(const int* __restrict__ d0, const int* __restrict__ d1,
                       const int* __restrict__ d2, int* __restrict__ o0,
                       int* __restrict__ o1, int* __restrict__ o2) {
    int i = blockIdx.x * blockDim.x + threadIdx.x;
    if (i < EPP) atomicAdd(&o0[d0[i] + 1], 1);
    else if (i < EPP + EAP) atomicAdd(&o1[d1[i - EPP] + 1], 1);
    else if (i < EPP + EAP + EPA) atomicAdd(&o2[d2[i - EPP - EAP] + 1], 1);
}
__device__ void scan_one(int* __restrict__ off, int* __restrict__ writer, int n, int nw) {
    __shared__ int ssum[1024];
    int tid = threadIdx.x;
    int running = 0;
    for (int base = 0; base < n; base += 4096) {
        int idx = base + tid * 4;
        int v0 = idx + 0 < n ? off[idx + 0] : 0;
        int v1 = idx + 1 < n ? off[idx + 1] : 0;
        int v2 = idx + 2 < n ? off[idx + 2] : 0;
        int v3 = idx + 3 < n ? off[idx + 3] : 0;
        int p0 = v0, p1 = p0 + v1, p2 = p1 + v2, p3 = p2 + v3;
        ssum[tid] = p3;
        __syncthreads();
        for (int o = 1; o < 1024; o <<= 1) {
            int val = 0;
            if (tid >= o) val = ssum[tid - o];
            __syncthreads();
            if (tid >= o) ssum[tid] += val;
            __syncthreads();
        }
        int excl = running + (tid ? ssum[tid - 1] : 0);
        int total = ssum[1023];
        __syncthreads();
        int s0 = excl + p0, s1 = excl + p1, s2 = excl + p2, s3 = excl + p3;
        if (idx + 0 < n) { off[idx + 0] = s0; if (idx + 0 < nw) writer[idx + 0] = s0; }
        if (idx + 1 < n) { off[idx + 1] = s1; if (idx + 1 < nw) writer[idx + 1] = s1; }
        if (idx + 2 < n) { off[idx + 2] = s2; if (idx + 2 < nw) writer[idx + 2] = s2; }
        if (idx + 3 < n) { off[idx + 3] = s3; if (idx + 3 < nw) writer[idx + 3] = s3; }
        running += total;
    }
}
__global__ void __launch_bounds__(1024)
scan3(int* __restrict__ o0, int* __restrict__ o1, int* __restrict__ o2,
      int* __restrict__ writer) {
    if (blockIdx.x == 0)      scan_one(o0, writer, NP + 1, NP);
    else if (blockIdx.x == 1) scan_one(o1, writer + NP, NP + 1, NP);
    else                      scan_one(o2, writer + 2 * NP, NA + 1, NA);
}
__global__ void scatter3(const int* __restrict__ s0, const int* __restrict__ d0,
                         const int* __restrict__ s1, const int* __restrict__ d1,
                         const int* __restrict__ s2, const int* __restrict__ d2,
                         int* __restrict__ writer, int* __restrict__ srt) {
    int i = blockIdx.x * blockDim.x + threadIdx.x;
    if (i < EPP) {
        int pos = atomicAdd(&writer[d0[i]], 1);
        srt[pos] = s0[i];
    } else if (i < EPP + EAP) {
        int e = i - EPP;
        int pos = atomicAdd(&writer[NP + d1[e]], 1);
        srt[EPP + pos] = s1[e];
    } else if (i < EPP + EAP + EPA) {
        int e = i - EPP - EAP;
        int pos = atomicAdd(&writer[2 * NP + d2[e]], 1);
        srt[EPP + EAP + pos] = s2[e];
    }
}

// ---------------- vd folding ---------------------------------------------------
__global__ void compute_vd(const float* __restrict__ Wd1, const float* __restrict__ ad1,
                           const float* __restrict__ Wd2, const float* __restrict__ ad2,
                           float* __restrict__ vd1, float* __restrict__ vd2) {
    int i = blockIdx.x * blockDim.x + threadIdx.x;
    if (i >= 2 * 3 * 128 * 4) return;
    int layer = i >= 3 * 128 * 4;
    int ii = i - layer * 3 * 128 * 4;
    int h = ii & 3;
    int f = (ii >> 2) & 127;
    int r = ii >> 9;
    int D = layer ? 64 : 128;
    int C = D / 4;
    const float* W = (layer ? Wd2 : Wd1) + (size_t)r * 128 * D + (size_t)f * D + h * C;
    const float* a = (layer ? ad2 : ad1) + r * 4 * C + h * C;
    float s = 0.f;
    for (int c = 0; c < C; c++) s += W[c] * a[c];
    (layer ? vd2 : vd1)[r * 512 + f * 4 + h] = s;
}

// ---------------- tf32 MMA GEMM + es epilogue + fused ed -----------------------
template <int CC, int NED>
__global__ void __launch_bounds__(256)
mma_es(const float* __restrict__ A, const float* __restrict__ B,
       __half* __restrict__ C, float* __restrict__ es,
       const float* __restrict__ a_s,
       const float* __restrict__ vdA, const float* __restrict__ vdB,
       float* __restrict__ edA, float* __restrict__ edB,
       int M, int N) {
    const int K = 128;
    const int BKc = 16;
    __shared__ __align__(16) float As[2][128][BKc + 4];
    __shared__ __align__(16) float Bs[2][BKc][64 + 8];
    __shared__ __align__(16) float vds[128][8];
    int tid = threadIdx.x;
    int lane = tid & 31, wid = tid >> 5;
    int wm = wid & 3, wn = wid >> 2;
    int g = lane >> 2, tig = lane & 3;
    int m0 = blockIdx.y * 128, n0 = blockIdx.x * 64;

    if (NED > 0) {
        for (int i = tid; i < 1024; i += 256) {
            int k = i >> 3, j = i & 7;
            float v = 0.f;
            if (j < 4) v = vdA[k * 4 + j];
            else if (NED == 2) v = vdB[k * 4 + (j - 4)];
            vds[k][j] = v;
        }
    }

    float cfr[2][4][4];
#pragma unroll
    for (int mt = 0; mt < 2; mt++)
#pragma unroll
        for (int nt = 0; nt < 4; nt++)
#pragma unroll
            for (int q = 0; q < 4; q++) cfr[mt][nt][q] = 0.f;
    float edf[2][4];
#pragma unroll
    for (int mt = 0; mt < 2; mt++)
#pragma unroll
        for (int q = 0; q < 4; q++) edf[mt][q] = 0.f;
    bool do_ed = (NED > 0) && (wn == 0) && (blockIdx.x == 0);

    int aRow = tid >> 1, aK = (tid & 1) * 8;
    int bRow = tid >> 4, bC = (tid & 15) * 4;

    float4 ra0, ra1, rb;
    auto loadg = [&](int k0) {
        int m = m0 + aRow;
        if (m < M) {
            ra0 = *(const float4*)(A + (size_t)m * K + k0 + aK);
            ra1 = *(const float4*)(A + (size_t)m * K + k0 + aK + 4);
        } else {
            ra0 = make_float4(0.f, 0.f, 0.f, 0.f);
            ra1 = ra0;
        }
        rb = *(const float4*)(B + (size_t)(k0 + bRow) * N + n0 + bC);
    };
    auto stores = [&](int buf) {
        *(float4*)&As[buf][aRow][aK] = ra0;
        *(float4*)&As[buf][aRow][aK + 4] = ra1;
        *(float4*)&Bs[buf][bRow][bC] = rb;
    };

    loadg(0);
    stores(0);
    __syncthreads();

#pragma unroll 1
    for (int c = 0; c < 8; c++) {
        if (c + 1 < 8) loadg((c + 1) * BKc);
        int buf = c & 1;
#pragma unroll
        for (int kk = 0; kk < BKc; kk += 8) {
            uint32_t af[2][4], bf[4][2];
#pragma unroll
            for (int mt = 0; mt < 2; mt++) {
                int rm = wm * 32 + mt * 16;
                af[mt][0] = tf32(As[buf][rm + g][kk + tig]);
                af[mt][1] = tf32(As[buf][rm + g + 8][kk + tig]);
                af[mt][2] = tf32(As[buf][rm + g][kk + tig + 4]);
                af[mt][3] = tf32(As[buf][rm + g + 8][kk + tig + 4]);
            }
#pragma unroll
            for (int nt = 0; nt < 4; nt++) {
                int cn = wn * 32 + nt * 8;
                bf[nt][0] = tf32(Bs[buf][kk + tig][cn + g]);
                bf[nt][1] = tf32(Bs[buf][kk + tig + 4][cn + g]);
            }
#pragma unroll
            for (int mt = 0; mt < 2; mt++)
#pragma unroll
                for (int nt = 0; nt < 4; nt++)
                    mma_tf32(cfr[mt][nt], af[mt], bf[nt]);
            if (do_ed) {
                uint32_t bvd[2];
                int kg = c * BKc + kk;
                bvd[0] = tf32(vds[kg + tig][g]);
                bvd[1] = tf32(vds[kg + tig + 4][g]);
                mma_tf32(edf[0], af[0], bvd);
                mma_tf32(edf[1], af[1], bvd);
            }
        }
        if (c + 1 < 8) stores((c + 1) & 1);
        __syncthreads();
    }

    if (do_ed) {
        auto edst = [&](int m, int col, float v) {
            int rel = col >> 2;
            if (rel == 1 && NED < 2) return;
            int h = col & 3;
            float* dst = rel ? edB : edA;
            if (m < M)
                *(float2*)(dst + m * 8 + h * 2) =
                    make_float2(__expf(v), __expf(0.2f * v));
        };
#pragma unroll
        for (int mt = 0; mt < 2; mt++) {
            int m_lo = m0 + wm * 32 + mt * 16 + g;
            int m_hi = m_lo + 8;
            edst(m_lo, 2 * tig + 0, edf[mt][0]);
            edst(m_lo, 2 * tig + 1, edf[mt][1]);
            edst(m_hi, 2 * tig + 0, edf[mt][2]);
            edst(m_hi, 2 * tig + 1, edf[mt][3]);
        }
    }

    {
        constexpr int NH = 32 / CC;
        float pl[2][NH], ph[2][NH];
#pragma unroll
        for (int mt = 0; mt < 2; mt++)
#pragma unroll
            for (int nh = 0; nh < NH; nh++) { pl[mt][nh] = 0.f; ph[mt][nh] = 0.f; }
#pragma unroll
        for (int nt = 0; nt < 4; nt++) {
            int nh = (nt * 8) / CC;
            float w0 = __ldg(&a_s[n0 + wn * 32 + nt * 8 + 2 * tig]);
            float w1 = __ldg(&a_s[n0 + wn * 32 + nt * 8 + 2 * tig + 1]);
#pragma unroll
            for (int mt = 0; mt < 2; mt++) {
                pl[mt][nh] += cfr[mt][nt][0] * w0 + cfr[mt][nt][1] * w1;
                ph[mt][nh] += cfr[mt][nt][2] * w0 + cfr[mt][nt][3] * w1;
            }
        }
#pragma unroll
        for (int mt = 0; mt < 2; mt++)
#pragma unroll
            for (int nh = 0; nh < NH; nh++) {
#pragma unroll
                for (int off = 1; off < 4; off <<= 1) {
                    pl[mt][nh] += __shfl_xor_sync(0xffffffffu, pl[mt][nh], off, 4);
                    ph[mt][nh] += __shfl_xor_sync(0xffffffffu, ph[mt][nh], off, 4);
                }
                if (tig == 0) {
                    int h = (n0 + wn * 32) / CC + nh;
                    int m_lo = m0 + wm * 32 + mt * 16 + g;
                    int m_hi = m_lo + 8;
                    if (m_lo < M)
                        *(float2*)(es + m_lo * 8 + h * 2) =
                            make_float2(__expf(pl[mt][nh]), __expf(0.2f * pl[mt][nh]));
                    if (m_hi < M)
                        *(float2*)(es + m_hi * 8 + h * 2) =
                            make_float2(__expf(ph[mt][nh]), __expf(0.2f * ph[mt][nh]));
                }
            }
    }

#pragma unroll
    for (int mt = 0; mt < 2; mt++) {
        int m_lo = m0 + wm * 32 + mt * 16 + g;
        int m_hi = m_lo + 8;
#pragma unroll
        for (int nt = 0; nt < 4; nt++) {
            int col = n0 + wn * 32 + nt * 8 + 2 * tig;
            if (m_lo < M)
                *(__half2*)(C + (size_t)m_lo * N + col) =
                    __floats2half2_rn(cfr[mt][nt][0], cfr[mt][nt][1]);
            if (m_hi < M)
                *(__half2*)(C + (size_t)m_hi * N + col) =
                    __floats2half2_rn(cfr[mt][nt][2], cfr[mt][nt][3]);
        }
    }
}

// -------- per-relation edge accumulation: ALL batches full-width (predicated) --
template <int D>
__device__ __forceinline__ void edge_accum(
        const int* __restrict__ off, const int* __restrict__ srt,
        const float* __restrict__ es, const float* __restrict__ ed,
        const __half* __restrict__ hs,
        int d, int lane, int h, float& den, float* a) {
    int start = __ldg(&off[d]), end = __ldg(&off[d + 1]);
    float2 edv = __ldg((const float2*)(ed + d * 8 + h * 2));
    float E1d = edv.x, E2d = edv.y;
    for (int i = start; i < end; i += 8) {
        int rem = end - i;   // >= 1
        int s[8];
#pragma unroll
        for (int j = 0; j < 8; j++) {
            int idx = (j < rem) ? i + j : i;   // clamp: duplicate loads, zeroed below
            s[j] = __ldg(&srt[idx]);
        }
        float2 v[8];
#pragma unroll
        for (int j = 0; j < 8; j++)
            v[j] = __ldg((const float2*)(es + s[j] * 8 + h * 2));
        if (D == 128) {
            uint2 u[8];
#pragma unroll
            for (int j = 0; j < 8; j++)
                u[j] = *(const uint2*)(hs + (size_t)s[j] * D + lane * 4);
#pragma unroll
            for (int j = 0; j < 8; j++) {
                float ee = (j < rem) ? fmaxf(v[j].x * E1d, v[j].y * E2d) : 0.f;
                den += ee;
                union { uint2 uu; __half2 h2[2]; } cv;
                cv.uu = u[j];
                float2 p0 = __half22float2(cv.h2[0]);
                float2 p1 = __half22float2(cv.h2[1]);
                a[0] += ee * p0.x; a[1] += ee * p0.y;
                a[2] += ee * p1.x; a[3] += ee * p1.y;
            }
        } else {
            unsigned u[8];
#pragma unroll
            for (int j = 0; j < 8; j++)
                u[j] = *(const unsigned*)(hs + (size_t)s[j] * D + lane * 2);
#pragma unroll
            for (int j = 0; j < 8; j++) {
                float ee = (j < rem) ? fmaxf(v[j].x * E1d, v[j].y * E2d) : 0.f;
                den += ee;
                union { unsigned uu; __half2 h2; } cv;
                cv.uu = u[j];
                float2 p = __half22float2(cv.h2);
                a[0] += ee * p.x; a[1] += ee * p.y;
            }
        }
    }
}

// -------- SINGLE gather over all dst nodes (paper: pp+ap; author: pa) ----------
template <int D>
__global__ void __launch_bounds__(256)
gat_gather_all(const int* __restrict__ off0, const int* __restrict__ srt0,
               const float* __restrict__ es0, const float* __restrict__ ed0,
               const __half* __restrict__ hs0,
               const int* __restrict__ off1, const int* __restrict__ srt1,
               const float* __restrict__ es1, const float* __restrict__ ed1,
               const __half* __restrict__ hs1,
               const int* __restrict__ off2, const int* __restrict__ srt2,
               const float* __restrict__ es2, const float* __restrict__ ed2,
               const __half* __restrict__ hs2,
               float* __restrict__ accP, float* __restrict__ accA,
               const float* __restrict__ bP0, const float* __restrict__ bP1,
               const float* __restrict__ bA0, int relu) {
    constexpr int CPL = D / 32;
    int warp = (blockIdx.x * blockDim.x + threadIdx.x) >> 5;
    int lane = threadIdx.x & 31;
    int h = lane >> 3;
    int cb = lane * CPL;
    if (warp < NP) {
        int d = warp;
        float denA = 0.f, denB = 0.f;
        float aA[4] = {0.f, 0.f, 0.f, 0.f}, aB[4] = {0.f, 0.f, 0.f, 0.f};
        edge_accum<D>(off0, srt0, es0, ed0, hs0, d, lane, h, denA, aA);
        edge_accum<D>(off1, srt1, es1, ed1, hs1, d, lane, h, denB, aB);
        float invA = 1.f / (denA + 1e-16f);
        float invB = 1.f / (denB + 1e-16f);
        float* dp = accP + (size_t)d * D + cb;
        if (D == 128) {
            float4 b0 = *(const float4*)(bP0 + cb);
            float4 b1 = *(const float4*)(bP1 + cb);
            float4 o = make_float4(aA[0] * invA + aB[0] * invB + b0.x + b1.x,
                                   aA[1] * invA + aB[1] * invB + b0.y + b1.y,
                                   aA[2] * invA + aB[2] * invB + b0.z + b1.z,
                                   aA[3] * invA + aB[3] * invB + b0.w + b1.w);
            if (relu) {
                o.x = fmaxf(o.x, 0.f); o.y = fmaxf(o.y, 0.f);
                o.z = fmaxf(o.z, 0.f); o.w = fmaxf(o.w, 0.f);
            }
            *(float4*)dp = o;
        } else {
            float2 b0 = *(const float2*)(bP0 + cb);
            float2 b1 = *(const float2*)(bP1 + cb);
            float2 o = make_float2(aA[0] * invA + aB[0] * invB + b0.x + b1.x,
                                   aA[1] * invA + aB[1] * invB + b0.y + b1.y);
            if (relu) { o.x = fmaxf(o.x, 0.f); o.y = fmaxf(o.y, 0.f); }
            *(float2*)dp = o;
        }
    } else if (warp < NP + NA) {
        int d = warp - NP;
        float den = 0.f;
        float a[4] = {0.f, 0.f, 0.f, 0.f};
        edge_accum<D>(off2, srt2, es2, ed2, hs2, d, lane, h, den, a);
        float inv = 1.f / (den + 1e-16f);
        float* dp = accA + (size_t)d * D + cb;
        if (D == 128) {
            float4 b0 = *(const float4*)(bA0 + cb);
            float4 o = make_float4(a[0] * inv + b0.x, a[1] * inv + b0.y,
                                   a[2] * inv + b0.z, a[3] * inv + b0.w);
            if (relu) {
                o.x = fmaxf(o.x, 0.f); o.y = fmaxf(o.y, 0.f);
                o.z = fmaxf(o.z, 0.f); o.w = fmaxf(o.w, 0.f);
            }
            *(float4*)dp = o;
        } else {
            float2 b0 = *(const float2*)(bA0 + cb);
            float2 o = make_float2(a[0] * inv + b0.x, a[1] * inv + b0.y);
            if (relu) { o.x = fmaxf(o.x, 0.f); o.y = fmaxf(o.y, 0.f); }
            *(float2*)dp = o;
        }
    }
}

// =============================================================================
extern "C" void kernel_launch(void* const* d_in, const int* in_sizes, int n_in,
                              void* d_out, int out_size) {
    const float* x_p = (const float*)d_in[0];
    const float* x_a = (const float*)d_in[1];
    const int* src_pp = (const int*)d_in[2];
    const int* dst_pp = (const int*)d_in[3];
    const int* src_ap = (const int*)d_in[4];
    const int* dst_ap = (const int*)d_in[5];
    const int* src_pa = (const int*)d_in[6];
    const int* dst_pa = (const int*)d_in[7];
    const float* Wsrc1 = (const float*)d_in[8];
    const float* Wdst1 = (const float*)d_in[9];
    const float* asrc1 = (const float*)d_in[10];
    const float* adst1 = (const float*)d_in[11];
    const float* b1 = (const float*)d_in[12];
    const float* Wsrc2 = (const float*)d_in[13];
    const float* Wdst2 = (const float*)d_in[14];
    const float* asrc2 = (const float*)d_in[15];
    const float* adst2 = (const float*)d_in[16];
    const float* b2 = (const float*)d_in[17];
    float* out = (float*)d_out;

    void* p;
    cudaGetSymbolAddress(&p, g_hs0);    __half* hs0 = (__half*)p;
    cudaGetSymbolAddress(&p, g_hs1);    __half* hs1 = (__half*)p;
    cudaGetSymbolAddress(&p, g_hs2);    __half* hs2 = (__half*)p;
    cudaGetSymbolAddress(&p, g_es);     float* es   = (float*)p;
    cudaGetSymbolAddress(&p, g_ed);     float* ed   = (float*)p;
    cudaGetSymbolAddress(&p, g_accp);   float* accp = (float*)p;
    cudaGetSymbolAddress(&p, g_acca);   float* acca = (float*)p;
    cudaGetSymbolAddress(&p, g_vd1);    float* vd1  = (float*)p;
    cudaGetSymbolAddress(&p, g_vd2);    float* vd2  = (float*)p;
    cudaGetSymbolAddress(&p, g_off_pp); int* off_pp = (int*)p;
    cudaGetSymbolAddress(&p, g_off_ap); int* off_ap = (int*)p;
    cudaGetSymbolAddress(&p, g_off_pa); int* off_pa = (int*)p;
    cudaGetSymbolAddress(&p, g_srt);    int* srt    = (int*)p;
    cudaGetSymbolAddress(&p, g_writer); int* writer = (int*)p;

    int* srt_pp = srt;
    int* srt_ap = srt + EPP;
    int* srt_pa = srt + EPP + EAP;

    float* es0 = es;
    float* es1 = es + NP * 8;
    float* es2 = es + 2 * NP * 8;
    float* ed0 = ed;
    float* ed1 = ed + NP * 8;
    float* ed2 = ed + 2 * NP * 8;

    const int TB = 256;
    auto blocks = [](long long n) { return (int)((n + 255) / 256); };

    // ---- forked stream: CSR build overlaps with vd + layer-1 GEMMs ----
    cudaStream_t s2;
    cudaStreamCreateWithFlags(&s2, cudaStreamNonBlocking);
    cudaEvent_t eFork, eJoin;
    cudaEventCreateWithFlags(&eFork, cudaEventDisableTiming);
    cudaEventCreateWithFlags(&eJoin, cudaEventDisableTiming);

    cudaEventRecord(eFork, 0);
    cudaStreamWaitEvent(s2, eFork, 0);

    // CSR chain on s2
    cudaMemsetAsync(off_pp, 0, (NP + 1) * sizeof(int), s2);
    cudaMemsetAsync(off_ap, 0, (NP + 1) * sizeof(int), s2);
    cudaMemsetAsync(off_pa, 0, (NA + 1) * sizeof(int), s2);
    count3<<<blocks(EPP + EAP + EPA), TB, 0, s2>>>(dst_pp, dst_ap, dst_pa,
                                                   off_pp, off_ap, off_pa);
    scan3<<<3, 1024, 0, s2>>>(off_pp, off_ap, off_pa, writer);
    scatter3<<<blocks(EPP + EAP + EPA), TB, 0, s2>>>(src_pp, dst_pp, src_ap, dst_ap,
                                                     src_pa, dst_pa, writer, srt);
    cudaEventRecord(eJoin, s2);

    // main stream: vd + layer-1 GEMMs (independent of CSR)
    compute_vd<<<blocks(2 * 3 * 128 * 4), TB>>>(Wdst1, adst1, Wdst2, adst2, vd1, vd2);
    {
        dim3 gP(2, (NP + 127) / 128), gA(2, (NA + 127) / 128);
        mma_es<32, 2><<<gP, 256>>>(x_p, Wsrc1 + 0 * 128 * 128, hs0, es0, asrc1 + 0 * 128,
                                   vd1 + 0 * 512, vd1 + 1 * 512, ed0, ed1, NP, 128);
        mma_es<32, 1><<<gA, 256>>>(x_a, Wsrc1 + 1 * 128 * 128, hs1, es1, asrc1 + 1 * 128,
                                   vd1 + 2 * 512, nullptr, ed2, nullptr, NA, 128);
        mma_es<32, 0><<<gP, 256>>>(x_p, Wsrc1 + 2 * 128 * 128, hs2, es2, asrc1 + 2 * 128,
                                   nullptr, nullptr, nullptr, nullptr, NP, 128);
    }
    cudaStreamWaitEvent(0, eJoin, 0);

    // layer-1 gather
    gat_gather_all<128><<<blocks((long long)(NP + NA) * 32), TB>>>(
        off_pp, srt_pp, es0, ed0, hs0,
        off_ap, srt_ap, es1, ed1, hs1,
        off_pa, srt_pa, es2, ed2, hs2,
        accp, acca, b1 + 0, b1 + 128, b1 + 256, 1);

    // ---------------- layer 2 (D=64) -> d_out ----------------
    {
        dim3 gP(1, (NP + 127) / 128), gA(1, (NA + 127) / 128);
        mma_es<16, 2><<<gP, 256>>>(accp, Wsrc2 + 0 * 128 * 64, hs0, es0, asrc2 + 0 * 64,
                                   vd2 + 0 * 512, vd2 + 1 * 512, ed0, ed1, NP, 64);
        mma_es<16, 1><<<gA, 256>>>(acca, Wsrc2 + 1 * 128 * 64, hs1, es1, asrc2 + 1 * 64,
                                   vd2 + 2 * 512, nullptr, ed2, nullptr, NA, 64);
        mma_es<16, 0><<<gP, 256>>>(accp, Wsrc2 + 2 * 128 * 64, hs2, es2, asrc2 + 2 * 64,
                                   nullptr, nullptr, nullptr, nullptr, NP, 64);
        gat_gather_all<64><<<blocks((long long)(NP + NA) * 32), TB>>>(
            off_pp, srt_pp, es0, ed0, hs0,
            off_ap, srt_ap, es1, ed1, hs1,
            off_pa, srt_pa, es2, ed2, hs2,
            out, out + (size_t)NP * 64, b2 + 0, b2 + 64, b2 + 128, 0);
    }
}